// round 11
// baseline (speedup 1.0000x reference)
#include <cuda_runtime.h>
#include <cuda_bf16.h>
#include <mma.h>

using namespace nvcuda;

#define BATCH 4
#define SEQ   4096
#define DIM   512
#define NTOK  (BATCH*SEQ)

// ---------------- scratch (__device__ globals; no allocations anywhere) ----------------
__device__ __nv_bfloat16 g_xhi[NTOK*DIM];
__device__ __nv_bfloat16 g_xlo[NTOK*DIM];
__device__ __nv_bfloat16 g_whi[3*DIM*DIM];
__device__ __nv_bfloat16 g_wlo[3*DIM*DIM];
__device__ __nv_bfloat16 g_qhi[NTOK*DIM];
__device__ __nv_bfloat16 g_qlo[NTOK*DIM];
__device__ __nv_bfloat16 g_khi[NTOK*DIM];
__device__ __nv_bfloat16 g_klo[NTOK*DIM];
__device__ __nv_bfloat16 g_vhi[NTOK*DIM];
__device__ __nv_bfloat16 g_vlo[NTOK*DIM];
__device__ float         g_scores[(size_t)BATCH*SEQ*SEQ];
__device__ __nv_bfloat16 g_phi[(size_t)BATCH*SEQ*SEQ];
__device__ __nv_bfloat16 g_plo[(size_t)BATCH*SEQ*SEQ];

// ---------------- fp32 -> bf16 hi/lo split ----------------
// which: 0 -> x, 1 -> Wq, 2 -> Wk, 3 -> Wv.  n2 = element count / 2 (float2 units)
__global__ __launch_bounds__(256) void split_kernel(const float* __restrict__ src,
                                                    int which, int n2) {
    int i = blockIdx.x * 256 + threadIdx.x;
    if (i >= n2) return;
    __nv_bfloat16 *hi, *lo;
    if (which == 0) { hi = g_xhi; lo = g_xlo; }
    else            { hi = g_whi + (which-1)*DIM*DIM; lo = g_wlo + (which-1)*DIM*DIM; }
    float2 v = reinterpret_cast<const float2*>(src)[i];
    __nv_bfloat16 h0 = __float2bfloat16(v.x);
    __nv_bfloat16 h1 = __float2bfloat16(v.y);
    float l0 = v.x - __bfloat162float(h0);
    float l1 = v.y - __bfloat162float(h1);
    reinterpret_cast<__nv_bfloat162*>(hi)[i] = __halves2bfloat162(h0, h1);
    reinterpret_cast<__nv_bfloat162*>(lo)[i] =
        __halves2bfloat162(__float2bfloat16(l0), __float2bfloat16(l1));
}

// ---------------- GEMM 1: QKV projection (NN), epilogue splits output to bf16 hi/lo ----------------
// C[NTOK, DIM] = X[NTOK, DIM] @ W[DIM, DIM] + bias ; blockIdx.z selects q/k/v
__global__ __launch_bounds__(256) void qkv_kernel(const float* __restrict__ bq,
                                                  const float* __restrict__ bk,
                                                  const float* __restrict__ bv) {
    __shared__ __nv_bfloat16 Ash[128*24];
    __shared__ __nv_bfloat16 Asl[128*24];
    __shared__ __nv_bfloat16 Bsh[16*80];
    __shared__ __nv_bfloat16 Bsl[16*80];
    __shared__ float         stage[8][16*20];

    const int z  = blockIdx.z;
    const int n0 = blockIdx.x * 64;
    const int i0 = blockIdx.y * 128;
    const int t  = threadIdx.x;
    const int wid = t >> 5, lane = t & 31;
    const int wm = wid >> 1, wn = wid & 1;

    const __nv_bfloat16* __restrict__ Agh = g_xhi;
    const __nv_bfloat16* __restrict__ Agl = g_xlo;
    const __nv_bfloat16* __restrict__ Bgh = g_whi + z*DIM*DIM;
    const __nv_bfloat16* __restrict__ Bgl = g_wlo + z*DIM*DIM;
    const float* bias = (z==0) ? bq : (z==1) ? bk : bv;
    __nv_bfloat16* Oh = (z==0) ? g_qhi : (z==1) ? g_khi : g_vhi;
    __nv_bfloat16* Ol = (z==0) ? g_qlo : (z==1) ? g_klo : g_vlo;

    wmma::fragment<wmma::accumulator,16,16,16,float> acc[2][2];
    #pragma unroll
    for (int mi=0; mi<2; mi++)
        #pragma unroll
        for (int ni=0; ni<2; ni++)
            wmma::fill_fragment(acc[mi][ni], 0.0f);

    const int arow = t >> 1, aseg = t & 1;        // A: 128 rows x 2 uint4 segs
    const int brow = t >> 3, bseg = t & 7;        // B: 16 rows x 8 uint4 segs (t<128)
    const bool bact = (t < 128);

    uint4 rAh, rAl, rBh, rBl;
    rAh = *reinterpret_cast<const uint4*>(Agh + (size_t)(i0+arow)*DIM + aseg*8);
    rAl = *reinterpret_cast<const uint4*>(Agl + (size_t)(i0+arow)*DIM + aseg*8);
    if (bact) {
        rBh = *reinterpret_cast<const uint4*>(Bgh + (size_t)brow*DIM + n0 + bseg*8);
        rBl = *reinterpret_cast<const uint4*>(Bgl + (size_t)brow*DIM + n0 + bseg*8);
    }

    const int KSTEPS = DIM/16;
    for (int kt = 0; kt < KSTEPS; kt++) {
        *reinterpret_cast<uint4*>(&Ash[arow*24 + aseg*8]) = rAh;
        *reinterpret_cast<uint4*>(&Asl[arow*24 + aseg*8]) = rAl;
        if (bact) {
            *reinterpret_cast<uint4*>(&Bsh[brow*80 + bseg*8]) = rBh;
            *reinterpret_cast<uint4*>(&Bsl[brow*80 + bseg*8]) = rBl;
        }
        __syncthreads();
        if (kt+1 < KSTEPS) {
            int k0 = (kt+1)*16;
            rAh = *reinterpret_cast<const uint4*>(Agh + (size_t)(i0+arow)*DIM + k0 + aseg*8);
            rAl = *reinterpret_cast<const uint4*>(Agl + (size_t)(i0+arow)*DIM + k0 + aseg*8);
            if (bact) {
                rBh = *reinterpret_cast<const uint4*>(Bgh + (size_t)(k0+brow)*DIM + n0 + bseg*8);
                rBl = *reinterpret_cast<const uint4*>(Bgl + (size_t)(k0+brow)*DIM + n0 + bseg*8);
            }
        }
        wmma::fragment<wmma::matrix_a,16,16,16,__nv_bfloat16,wmma::row_major> fah[2], fal[2];
        wmma::fragment<wmma::matrix_b,16,16,16,__nv_bfloat16,wmma::row_major> fbh[2], fbl[2];
        #pragma unroll
        for (int mi=0; mi<2; mi++) {
            wmma::load_matrix_sync(fah[mi], &Ash[(wm*32+mi*16)*24], 24);
            wmma::load_matrix_sync(fal[mi], &Asl[(wm*32+mi*16)*24], 24);
        }
        #pragma unroll
        for (int ni=0; ni<2; ni++) {
            wmma::load_matrix_sync(fbh[ni], &Bsh[wn*32+ni*16], 80);
            wmma::load_matrix_sync(fbl[ni], &Bsl[wn*32+ni*16], 80);
        }
        #pragma unroll
        for (int mi=0; mi<2; mi++)
            #pragma unroll
            for (int ni=0; ni<2; ni++) {
                wmma::mma_sync(acc[mi][ni], fah[mi], fbh[ni], acc[mi][ni]);
                wmma::mma_sync(acc[mi][ni], fah[mi], fbl[ni], acc[mi][ni]);
                wmma::mma_sync(acc[mi][ni], fal[mi], fbh[ni], acc[mi][ni]);
            }
        __syncthreads();
    }

    // epilogue: stage each 16x16 fragment, add bias, split to bf16 hi/lo
    #pragma unroll
    for (int mi=0; mi<2; mi++)
        #pragma unroll
        for (int ni=0; ni<2; ni++) {
            float* buf = stage[wid];
            wmma::store_matrix_sync(buf, acc[mi][ni], 20, wmma::mem_row_major);
            __syncwarp();
            int gi = i0 + wm*32 + mi*16;
            int gn = n0 + wn*32 + ni*16;
            for (int e = lane; e < 256; e += 32) {
                int r = e >> 4, c = e & 15;
                float v = buf[r*20 + c] + bias[gn + c];
                __nv_bfloat16 h = __float2bfloat16(v);
                float l = v - __bfloat162float(h);
                size_t off = (size_t)(gi + r)*DIM + gn + c;
                Oh[off] = h;
                Ol[off] = __float2bfloat16(l);
            }
            __syncwarp();
        }
}

// ---------------- GEMM 2: scores = Q @ K^T * 0.5 (NT) ----------------
__global__ __launch_bounds__(256) void scores_kernel() {
    __shared__ __nv_bfloat16 Ash[128*24];
    __shared__ __nv_bfloat16 Asl[128*24];
    __shared__ __nv_bfloat16 Bsh[64*24];
    __shared__ __nv_bfloat16 Bsl[64*24];

    const int b  = blockIdx.z;
    const int j0 = blockIdx.x * 64;
    const int i0 = blockIdx.y * 128;
    const int t  = threadIdx.x;
    const int wid = t >> 5;
    const int wm = wid >> 1, wn = wid & 1;

    const __nv_bfloat16* __restrict__ Agh = g_qhi + (size_t)b*SEQ*DIM;
    const __nv_bfloat16* __restrict__ Agl = g_qlo + (size_t)b*SEQ*DIM;
    const __nv_bfloat16* __restrict__ Bgh = g_khi + (size_t)b*SEQ*DIM;
    const __nv_bfloat16* __restrict__ Bgl = g_klo + (size_t)b*SEQ*DIM;

    wmma::fragment<wmma::accumulator,16,16,16,float> acc[2][2];
    #pragma unroll
    for (int mi=0; mi<2; mi++)
        #pragma unroll
        for (int ni=0; ni<2; ni++)
            wmma::fill_fragment(acc[mi][ni], 0.0f);

    const int arow = t >> 1, aseg = t & 1;
    const int brow = t >> 1, bseg = t & 1;   // B: 64 rows x 2 segs (t<128)
    const bool bact = (t < 128);

    uint4 rAh, rAl, rBh, rBl;
    rAh = *reinterpret_cast<const uint4*>(Agh + (size_t)(i0+arow)*DIM + aseg*8);
    rAl = *reinterpret_cast<const uint4*>(Agl + (size_t)(i0+arow)*DIM + aseg*8);
    if (bact) {
        rBh = *reinterpret_cast<const uint4*>(Bgh + (size_t)(j0+brow)*DIM + bseg*8);
        rBl = *reinterpret_cast<const uint4*>(Bgl + (size_t)(j0+brow)*DIM + bseg*8);
    }

    const int KSTEPS = DIM/16;
    for (int kt = 0; kt < KSTEPS; kt++) {
        *reinterpret_cast<uint4*>(&Ash[arow*24 + aseg*8]) = rAh;
        *reinterpret_cast<uint4*>(&Asl[arow*24 + aseg*8]) = rAl;
        if (bact) {
            *reinterpret_cast<uint4*>(&Bsh[brow*24 + bseg*8]) = rBh;
            *reinterpret_cast<uint4*>(&Bsl[brow*24 + bseg*8]) = rBl;
        }
        __syncthreads();
        if (kt+1 < KSTEPS) {
            int k0 = (kt+1)*16;
            rAh = *reinterpret_cast<const uint4*>(Agh + (size_t)(i0+arow)*DIM + k0 + aseg*8);
            rAl = *reinterpret_cast<const uint4*>(Agl + (size_t)(i0+arow)*DIM + k0 + aseg*8);
            if (bact) {
                rBh = *reinterpret_cast<const uint4*>(Bgh + (size_t)(j0+brow)*DIM + k0 + bseg*8);
                rBl = *reinterpret_cast<const uint4*>(Bgl + (size_t)(j0+brow)*DIM + k0 + bseg*8);
            }
        }
        wmma::fragment<wmma::matrix_a,16,16,16,__nv_bfloat16,wmma::row_major> fah[2], fal[2];
        wmma::fragment<wmma::matrix_b,16,16,16,__nv_bfloat16,wmma::col_major> fbh[2], fbl[2];
        #pragma unroll
        for (int mi=0; mi<2; mi++) {
            wmma::load_matrix_sync(fah[mi], &Ash[(wm*32+mi*16)*24], 24);
            wmma::load_matrix_sync(fal[mi], &Asl[(wm*32+mi*16)*24], 24);
        }
        #pragma unroll
        for (int ni=0; ni<2; ni++) {
            wmma::load_matrix_sync(fbh[ni], &Bsh[(wn*32+ni*16)*24], 24);
            wmma::load_matrix_sync(fbl[ni], &Bsl[(wn*32+ni*16)*24], 24);
        }
        #pragma unroll
        for (int mi=0; mi<2; mi++)
            #pragma unroll
            for (int ni=0; ni<2; ni++) {
                wmma::mma_sync(acc[mi][ni], fah[mi], fbh[ni], acc[mi][ni]);
                wmma::mma_sync(acc[mi][ni], fah[mi], fbl[ni], acc[mi][ni]);
                wmma::mma_sync(acc[mi][ni], fal[mi], fbh[ni], acc[mi][ni]);
            }
        __syncthreads();
    }

    // epilogue: scale by 0.5 (scale = batch/2 = 2 -> divide), store fp32
    #pragma unroll
    for (int mi=0; mi<2; mi++)
        #pragma unroll
        for (int ni=0; ni<2; ni++) {
            #pragma unroll
            for (int e = 0; e < acc[mi][ni].num_elements; e++)
                acc[mi][ni].x[e] *= 0.5f;
            float* Cp = g_scores + (size_t)b*SEQ*SEQ
                        + (size_t)(i0 + wm*32 + mi*16)*SEQ + (j0 + wn*32 + ni*16);
            wmma::store_matrix_sync(Cp, acc[mi][ni], SEQ, wmma::mem_row_major);
        }
}

// ---------------- softmax over rows of 4096, writes P as bf16 hi/lo ----------------
__global__ __launch_bounds__(256) void softmax_kernel() {
    __shared__ float red[40];
    const int t = threadIdx.x;
    const int lane = t & 31, warp = t >> 5;
    size_t base = (size_t)blockIdx.x * SEQ;
    const float4* src4 = reinterpret_cast<const float4*>(g_scores + base);

    float4 v[4];
    float mx = -3.0e38f;
    #pragma unroll
    for (int q = 0; q < 4; q++) {
        v[q] = src4[t + 256*q];
        mx = fmaxf(mx, fmaxf(fmaxf(v[q].x, v[q].y), fmaxf(v[q].z, v[q].w)));
    }
    #pragma unroll
    for (int o = 16; o > 0; o >>= 1) mx = fmaxf(mx, __shfl_xor_sync(0xffffffffu, mx, o));
    if (lane == 0) red[warp] = mx;
    __syncthreads();
    if (t == 0) {
        float m = red[0];
        #pragma unroll
        for (int w = 1; w < 8; w++) m = fmaxf(m, red[w]);
        red[32] = m;
    }
    __syncthreads();
    mx = red[32];

    float sum = 0.0f;
    #pragma unroll
    for (int q = 0; q < 4; q++) {
        v[q].x = expf(v[q].x - mx);
        v[q].y = expf(v[q].y - mx);
        v[q].z = expf(v[q].z - mx);
        v[q].w = expf(v[q].w - mx);
        sum += (v[q].x + v[q].y) + (v[q].z + v[q].w);
    }
    #pragma unroll
    for (int o = 16; o > 0; o >>= 1) sum += __shfl_xor_sync(0xffffffffu, sum, o);
    if (lane == 0) red[8 + warp] = sum;
    __syncthreads();
    if (t == 0) {
        float s = 0.0f;
        #pragma unroll
        for (int w = 0; w < 8; w++) s += red[8 + w];
        red[33] = 1.0f / s;
    }
    __syncthreads();
    float inv = red[33];

    __nv_bfloat162* ph = reinterpret_cast<__nv_bfloat162*>(g_phi + base);
    __nv_bfloat162* pl = reinterpret_cast<__nv_bfloat162*>(g_plo + base);
    #pragma unroll
    for (int q = 0; q < 4; q++) {
        float p0 = v[q].x * inv, p1 = v[q].y * inv, p2 = v[q].z * inv, p3 = v[q].w * inv;
        __nv_bfloat16 h0 = __float2bfloat16(p0), h1 = __float2bfloat16(p1);
        __nv_bfloat16 h2 = __float2bfloat16(p2), h3 = __float2bfloat16(p3);
        float l0 = p0 - __bfloat162float(h0), l1 = p1 - __bfloat162float(h1);
        float l2 = p2 - __bfloat162float(h2), l3 = p3 - __bfloat162float(h3);
        int pi = 2*(t + 256*q);
        ph[pi]   = __halves2bfloat162(h0, h1);
        ph[pi+1] = __halves2bfloat162(h2, h3);
        pl[pi]   = __halves2bfloat162(__float2bfloat16(l0), __float2bfloat16(l1));
        pl[pi+1] = __halves2bfloat162(__float2bfloat16(l2), __float2bfloat16(l3));
    }
}

// ---------------- GEMM 3: Z = P @ V (NN), K = 4096, fp32 out ----------------
__global__ __launch_bounds__(256) void z_kernel(float* __restrict__ out) {
    __shared__ __nv_bfloat16 Ash[128*24];
    __shared__ __nv_bfloat16 Asl[128*24];
    __shared__ __nv_bfloat16 Bsh[16*80];
    __shared__ __nv_bfloat16 Bsl[16*80];

    const int b  = blockIdx.z;
    const int n0 = blockIdx.x * 64;
    const int i0 = blockIdx.y * 128;
    const int t  = threadIdx.x;
    const int wid = t >> 5;
    const int wm = wid >> 1, wn = wid & 1;

    const __nv_bfloat16* __restrict__ Agh = g_phi + (size_t)b*SEQ*SEQ;
    const __nv_bfloat16* __restrict__ Agl = g_plo + (size_t)b*SEQ*SEQ;
    const __nv_bfloat16* __restrict__ Bgh = g_vhi + (size_t)b*SEQ*DIM;
    const __nv_bfloat16* __restrict__ Bgl = g_vlo + (size_t)b*SEQ*DIM;

    wmma::fragment<wmma::accumulator,16,16,16,float> acc[2][2];
    #pragma unroll
    for (int mi=0; mi<2; mi++)
        #pragma unroll
        for (int ni=0; ni<2; ni++)
            wmma::fill_fragment(acc[mi][ni], 0.0f);

    const int arow = t >> 1, aseg = t & 1;
    const int brow = t >> 3, bseg = t & 7;
    const bool bact = (t < 128);

    uint4 rAh, rAl, rBh, rBl;
    rAh = *reinterpret_cast<const uint4*>(Agh + (size_t)(i0+arow)*SEQ + aseg*8);
    rAl = *reinterpret_cast<const uint4*>(Agl + (size_t)(i0+arow)*SEQ + aseg*8);
    if (bact) {
        rBh = *reinterpret_cast<const uint4*>(Bgh + (size_t)brow*DIM + n0 + bseg*8);
        rBl = *reinterpret_cast<const uint4*>(Bgl + (size_t)brow*DIM + n0 + bseg*8);
    }

    const int KSTEPS = SEQ/16;
    for (int kt = 0; kt < KSTEPS; kt++) {
        *reinterpret_cast<uint4*>(&Ash[arow*24 + aseg*8]) = rAh;
        *reinterpret_cast<uint4*>(&Asl[arow*24 + aseg*8]) = rAl;
        if (bact) {
            *reinterpret_cast<uint4*>(&Bsh[brow*80 + bseg*8]) = rBh;
            *reinterpret_cast<uint4*>(&Bsl[brow*80 + bseg*8]) = rBl;
        }
        __syncthreads();
        if (kt+1 < KSTEPS) {
            int k0 = (kt+1)*16;
            rAh = *reinterpret_cast<const uint4*>(Agh + (size_t)(i0+arow)*SEQ + k0 + aseg*8);
            rAl = *reinterpret_cast<const uint4*>(Agl + (size_t)(i0+arow)*SEQ + k0 + aseg*8);
            if (bact) {
                rBh = *reinterpret_cast<const uint4*>(Bgh + (size_t)(k0+brow)*DIM + n0 + bseg*8);
                rBl = *reinterpret_cast<const uint4*>(Bgl + (size_t)(k0+brow)*DIM + n0 + bseg*8);
            }
        }
        wmma::fragment<wmma::matrix_a,16,16,16,__nv_bfloat16,wmma::row_major> fah[2], fal[2];
        wmma::fragment<wmma::matrix_b,16,16,16,__nv_bfloat16,wmma::row_major> fbh[2], fbl[2];
        #pragma unroll
        for (int mi=0; mi<2; mi++) {
            wmma::load_matrix_sync(fah[mi], &Ash[(wm*32+mi*16)*24], 24);
            wmma::load_matrix_sync(fal[mi], &Asl[(wm*32+mi*16)*24], 24);
        }
        #pragma unroll
        for (int ni=0; ni<2; ni++) {
            wmma::load_matrix_sync(fbh[ni], &Bsh[wn*32+ni*16], 80);
            wmma::load_matrix_sync(fbl[ni], &Bsl[wn*32+ni*16], 80);
        }
        #pragma unroll
        for (int mi=0; mi<2; mi++)
            #pragma unroll
            for (int ni=0; ni<2; ni++) {
                wmma::mma_sync(acc[mi][ni], fah[mi], fbh[ni], acc[mi][ni]);
                wmma::mma_sync(acc[mi][ni], fah[mi], fbl[ni], acc[mi][ni]);
                wmma::mma_sync(acc[mi][ni], fal[mi], fbh[ni], acc[mi][ni]);
            }
        __syncthreads();
    }

    #pragma unroll
    for (int mi=0; mi<2; mi++)
        #pragma unroll
        for (int ni=0; ni<2; ni++) {
            float* Cp = out + (size_t)b*SEQ*DIM
                        + (size_t)(i0 + wm*32 + mi*16)*DIM + (n0 + wn*32 + ni*16);
            wmma::store_matrix_sync(Cp, acc[mi][ni], DIM, wmma::mem_row_major);
        }
}

// ---------------- launch ----------------
extern "C" void kernel_launch(void* const* d_in, const int* in_sizes, int n_in,
                              void* d_out, int out_size) {
    (void)in_sizes; (void)n_in; (void)out_size;
    const float* x  = (const float*)d_in[0];
    const float* Wq = (const float*)d_in[1];
    const float* bq = (const float*)d_in[2];
    const float* Wk = (const float*)d_in[3];
    const float* bk = (const float*)d_in[4];
    const float* Wv = (const float*)d_in[5];
    const float* bv = (const float*)d_in[6];
    float* out = (float*)d_out;

    const int nx2 = NTOK*DIM/2;
    const int nw2 = DIM*DIM/2;
    split_kernel<<<(nx2 + 255)/256, 256>>>(x,  0, nx2);
    split_kernel<<<(nw2 + 255)/256, 256>>>(Wq, 1, nw2);
    split_kernel<<<(nw2 + 255)/256, 256>>>(Wk, 2, nw2);
    split_kernel<<<(nw2 + 255)/256, 256>>>(Wv, 3, nw2);

    qkv_kernel<<<dim3(DIM/64, NTOK/128, 3), 256>>>(bq, bk, bv);
    scores_kernel<<<dim3(SEQ/64, SEQ/128, BATCH), 256>>>();
    softmax_kernel<<<NTOK, 256>>>();
    z_kernel<<<dim3(DIM/64, SEQ/128, BATCH), 256>>>(out);
}

// round 12
// speedup vs baseline: 1.0007x; 1.0007x over previous
#include <cuda_runtime.h>
#include <cuda_bf16.h>
#include <mma.h>

using namespace nvcuda;

#define BATCH 4
#define SEQ   4096
#define DIM   512
#define NTOK  (BATCH*SEQ)

// ---------------- scratch (__device__ globals; no allocations anywhere) ----------------
__device__ __nv_bfloat16 g_xhi[NTOK*DIM];
__device__ __nv_bfloat16 g_xlo[NTOK*DIM];
__device__ __nv_bfloat16 g_whi[3*DIM*DIM];
__device__ __nv_bfloat16 g_wlo[3*DIM*DIM];
__device__ __nv_bfloat16 g_qhi[NTOK*DIM];
__device__ __nv_bfloat16 g_qlo[NTOK*DIM];
__device__ __nv_bfloat16 g_khi[NTOK*DIM];
__device__ __nv_bfloat16 g_klo[NTOK*DIM];
__device__ __nv_bfloat16 g_vhi[NTOK*DIM];
__device__ __nv_bfloat16 g_vlo[NTOK*DIM];
__device__ float         g_scores[(size_t)BATCH*SEQ*SEQ];
__device__ __nv_bfloat16 g_phi[(size_t)BATCH*SEQ*SEQ];
__device__ __nv_bfloat16 g_plo[(size_t)BATCH*SEQ*SEQ];

// ---------------- fp32 -> bf16 hi/lo split ----------------
// which: 0 -> x, 1 -> Wq, 2 -> Wk, 3 -> Wv.  n2 = element count / 2 (float2 units)
__global__ __launch_bounds__(256) void split_kernel(const float* __restrict__ src,
                                                    int which, int n2) {
    int i = blockIdx.x * 256 + threadIdx.x;
    if (i >= n2) return;
    __nv_bfloat16 *hi, *lo;
    if (which == 0) { hi = g_xhi; lo = g_xlo; }
    else            { hi = g_whi + (which-1)*DIM*DIM; lo = g_wlo + (which-1)*DIM*DIM; }
    float2 v = reinterpret_cast<const float2*>(src)[i];
    __nv_bfloat16 h0 = __float2bfloat16(v.x);
    __nv_bfloat16 h1 = __float2bfloat16(v.y);
    float l0 = v.x - __bfloat162float(h0);
    float l1 = v.y - __bfloat162float(h1);
    reinterpret_cast<__nv_bfloat162*>(hi)[i] = __halves2bfloat162(h0, h1);
    reinterpret_cast<__nv_bfloat162*>(lo)[i] =
        __halves2bfloat162(__float2bfloat16(l0), __float2bfloat16(l1));
}

// ---------------- GEMM 1: QKV projection (NN), epilogue splits output to bf16 hi/lo ----------------
// C[NTOK, DIM] = X[NTOK, DIM] @ W[DIM, DIM] + bias ; blockIdx.z selects q/k/v
__global__ __launch_bounds__(256) void qkv_kernel(const float* __restrict__ bq,
                                                  const float* __restrict__ bk,
                                                  const float* __restrict__ bv) {
    __shared__ __nv_bfloat16 Ash[128*24];
    __shared__ __nv_bfloat16 Asl[128*24];
    __shared__ __nv_bfloat16 Bsh[16*80];
    __shared__ __nv_bfloat16 Bsl[16*80];
    __shared__ float         stage[8][16*20];

    const int z  = blockIdx.z;
    const int n0 = blockIdx.x * 64;
    const int i0 = blockIdx.y * 128;
    const int t  = threadIdx.x;
    const int wid = t >> 5, lane = t & 31;
    const int wm = wid >> 1, wn = wid & 1;

    const __nv_bfloat16* __restrict__ Agh = g_xhi;
    const __nv_bfloat16* __restrict__ Agl = g_xlo;
    const __nv_bfloat16* __restrict__ Bgh = g_whi + z*DIM*DIM;
    const __nv_bfloat16* __restrict__ Bgl = g_wlo + z*DIM*DIM;
    const float* bias = (z==0) ? bq : (z==1) ? bk : bv;
    __nv_bfloat16* Oh = (z==0) ? g_qhi : (z==1) ? g_khi : g_vhi;
    __nv_bfloat16* Ol = (z==0) ? g_qlo : (z==1) ? g_klo : g_vlo;

    wmma::fragment<wmma::accumulator,16,16,16,float> acc[2][2];
    #pragma unroll
    for (int mi=0; mi<2; mi++)
        #pragma unroll
        for (int ni=0; ni<2; ni++)
            wmma::fill_fragment(acc[mi][ni], 0.0f);

    const int arow = t >> 1, aseg = t & 1;        // A: 128 rows x 2 uint4 segs
    const int brow = t >> 3, bseg = t & 7;        // B: 16 rows x 8 uint4 segs (t<128)
    const bool bact = (t < 128);

    uint4 rAh, rAl, rBh, rBl;
    rAh = *reinterpret_cast<const uint4*>(Agh + (size_t)(i0+arow)*DIM + aseg*8);
    rAl = *reinterpret_cast<const uint4*>(Agl + (size_t)(i0+arow)*DIM + aseg*8);
    if (bact) {
        rBh = *reinterpret_cast<const uint4*>(Bgh + (size_t)brow*DIM + n0 + bseg*8);
        rBl = *reinterpret_cast<const uint4*>(Bgl + (size_t)brow*DIM + n0 + bseg*8);
    }

    const int KSTEPS = DIM/16;
    for (int kt = 0; kt < KSTEPS; kt++) {
        *reinterpret_cast<uint4*>(&Ash[arow*24 + aseg*8]) = rAh;
        *reinterpret_cast<uint4*>(&Asl[arow*24 + aseg*8]) = rAl;
        if (bact) {
            *reinterpret_cast<uint4*>(&Bsh[brow*80 + bseg*8]) = rBh;
            *reinterpret_cast<uint4*>(&Bsl[brow*80 + bseg*8]) = rBl;
        }
        __syncthreads();
        if (kt+1 < KSTEPS) {
            int k0 = (kt+1)*16;
            rAh = *reinterpret_cast<const uint4*>(Agh + (size_t)(i0+arow)*DIM + k0 + aseg*8);
            rAl = *reinterpret_cast<const uint4*>(Agl + (size_t)(i0+arow)*DIM + k0 + aseg*8);
            if (bact) {
                rBh = *reinterpret_cast<const uint4*>(Bgh + (size_t)(k0+brow)*DIM + n0 + bseg*8);
                rBl = *reinterpret_cast<const uint4*>(Bgl + (size_t)(k0+brow)*DIM + n0 + bseg*8);
            }
        }
        wmma::fragment<wmma::matrix_a,16,16,16,__nv_bfloat16,wmma::row_major> fah[2], fal[2];
        wmma::fragment<wmma::matrix_b,16,16,16,__nv_bfloat16,wmma::row_major> fbh[2], fbl[2];
        #pragma unroll
        for (int mi=0; mi<2; mi++) {
            wmma::load_matrix_sync(fah[mi], &Ash[(wm*32+mi*16)*24], 24);
            wmma::load_matrix_sync(fal[mi], &Asl[(wm*32+mi*16)*24], 24);
        }
        #pragma unroll
        for (int ni=0; ni<2; ni++) {
            wmma::load_matrix_sync(fbh[ni], &Bsh[wn*32+ni*16], 80);
            wmma::load_matrix_sync(fbl[ni], &Bsl[wn*32+ni*16], 80);
        }
        #pragma unroll
        for (int mi=0; mi<2; mi++)
            #pragma unroll
            for (int ni=0; ni<2; ni++) {
                wmma::mma_sync(acc[mi][ni], fah[mi], fbh[ni], acc[mi][ni]);
                wmma::mma_sync(acc[mi][ni], fah[mi], fbl[ni], acc[mi][ni]);
                wmma::mma_sync(acc[mi][ni], fal[mi], fbh[ni], acc[mi][ni]);
            }
        __syncthreads();
    }

    // epilogue: stage each 16x16 fragment, add bias, split to bf16 hi/lo
    #pragma unroll
    for (int mi=0; mi<2; mi++)
        #pragma unroll
        for (int ni=0; ni<2; ni++) {
            float* buf = stage[wid];
            wmma::store_matrix_sync(buf, acc[mi][ni], 20, wmma::mem_row_major);
            __syncwarp();
            int gi = i0 + wm*32 + mi*16;
            int gn = n0 + wn*32 + ni*16;
            for (int e = lane; e < 256; e += 32) {
                int r = e >> 4, c = e & 15;
                float v = buf[r*20 + c] + bias[gn + c];
                __nv_bfloat16 h = __float2bfloat16(v);
                float l = v - __bfloat162float(h);
                size_t off = (size_t)(gi + r)*DIM + gn + c;
                Oh[off] = h;
                Ol[off] = __float2bfloat16(l);
            }
            __syncwarp();
        }
}

// ---------------- GEMM 2: scores = Q @ K^T * 0.5 (NT) ----------------
__global__ __launch_bounds__(256) void scores_kernel() {
    __shared__ __nv_bfloat16 Ash[128*24];
    __shared__ __nv_bfloat16 Asl[128*24];
    __shared__ __nv_bfloat16 Bsh[64*24];
    __shared__ __nv_bfloat16 Bsl[64*24];

    const int b  = blockIdx.z;
    const int j0 = blockIdx.x * 64;
    const int i0 = blockIdx.y * 128;
    const int t  = threadIdx.x;
    const int wid = t >> 5;
    const int wm = wid >> 1, wn = wid & 1;

    const __nv_bfloat16* __restrict__ Agh = g_qhi + (size_t)b*SEQ*DIM;
    const __nv_bfloat16* __restrict__ Agl = g_qlo + (size_t)b*SEQ*DIM;
    const __nv_bfloat16* __restrict__ Bgh = g_khi + (size_t)b*SEQ*DIM;
    const __nv_bfloat16* __restrict__ Bgl = g_klo + (size_t)b*SEQ*DIM;

    wmma::fragment<wmma::accumulator,16,16,16,float> acc[2][2];
    #pragma unroll
    for (int mi=0; mi<2; mi++)
        #pragma unroll
        for (int ni=0; ni<2; ni++)
            wmma::fill_fragment(acc[mi][ni], 0.0f);

    const int arow = t >> 1, aseg = t & 1;
    const int brow = t >> 1, bseg = t & 1;   // B: 64 rows x 2 segs (t<128)
    const bool bact = (t < 128);

    uint4 rAh, rAl, rBh, rBl;
    rAh = *reinterpret_cast<const uint4*>(Agh + (size_t)(i0+arow)*DIM + aseg*8);
    rAl = *reinterpret_cast<const uint4*>(Agl + (size_t)(i0+arow)*DIM + aseg*8);
    if (bact) {
        rBh = *reinterpret_cast<const uint4*>(Bgh + (size_t)(j0+brow)*DIM + bseg*8);
        rBl = *reinterpret_cast<const uint4*>(Bgl + (size_t)(j0+brow)*DIM + bseg*8);
    }

    const int KSTEPS = DIM/16;
    for (int kt = 0; kt < KSTEPS; kt++) {
        *reinterpret_cast<uint4*>(&Ash[arow*24 + aseg*8]) = rAh;
        *reinterpret_cast<uint4*>(&Asl[arow*24 + aseg*8]) = rAl;
        if (bact) {
            *reinterpret_cast<uint4*>(&Bsh[brow*24 + bseg*8]) = rBh;
            *reinterpret_cast<uint4*>(&Bsl[brow*24 + bseg*8]) = rBl;
        }
        __syncthreads();
        if (kt+1 < KSTEPS) {
            int k0 = (kt+1)*16;
            rAh = *reinterpret_cast<const uint4*>(Agh + (size_t)(i0+arow)*DIM + k0 + aseg*8);
            rAl = *reinterpret_cast<const uint4*>(Agl + (size_t)(i0+arow)*DIM + k0 + aseg*8);
            if (bact) {
                rBh = *reinterpret_cast<const uint4*>(Bgh + (size_t)(j0+brow)*DIM + k0 + bseg*8);
                rBl = *reinterpret_cast<const uint4*>(Bgl + (size_t)(j0+brow)*DIM + k0 + bseg*8);
            }
        }
        wmma::fragment<wmma::matrix_a,16,16,16,__nv_bfloat16,wmma::row_major> fah[2], fal[2];
        wmma::fragment<wmma::matrix_b,16,16,16,__nv_bfloat16,wmma::col_major> fbh[2], fbl[2];
        #pragma unroll
        for (int mi=0; mi<2; mi++) {
            wmma::load_matrix_sync(fah[mi], &Ash[(wm*32+mi*16)*24], 24);
            wmma::load_matrix_sync(fal[mi], &Asl[(wm*32+mi*16)*24], 24);
        }
        #pragma unroll
        for (int ni=0; ni<2; ni++) {
            wmma::load_matrix_sync(fbh[ni], &Bsh[(wn*32+ni*16)*24], 24);
            wmma::load_matrix_sync(fbl[ni], &Bsl[(wn*32+ni*16)*24], 24);
        }
        #pragma unroll
        for (int mi=0; mi<2; mi++)
            #pragma unroll
            for (int ni=0; ni<2; ni++) {
                wmma::mma_sync(acc[mi][ni], fah[mi], fbh[ni], acc[mi][ni]);
                wmma::mma_sync(acc[mi][ni], fah[mi], fbl[ni], acc[mi][ni]);
                wmma::mma_sync(acc[mi][ni], fal[mi], fbh[ni], acc[mi][ni]);
            }
        __syncthreads();
    }

    // epilogue: scale by 0.5 (scale = batch/2 = 2 -> divide), store fp32
    #pragma unroll
    for (int mi=0; mi<2; mi++)
        #pragma unroll
        for (int ni=0; ni<2; ni++) {
            #pragma unroll
            for (int e = 0; e < acc[mi][ni].num_elements; e++)
                acc[mi][ni].x[e] *= 0.5f;
            float* Cp = g_scores + (size_t)b*SEQ*SEQ
                        + (size_t)(i0 + wm*32 + mi*16)*SEQ + (j0 + wn*32 + ni*16);
            wmma::store_matrix_sync(Cp, acc[mi][ni], SEQ, wmma::mem_row_major);
        }
}

// ---------------- softmax over rows of 4096, writes P as bf16 hi/lo ----------------
__global__ __launch_bounds__(256) void softmax_kernel() {
    __shared__ float red[40];
    const int t = threadIdx.x;
    const int lane = t & 31, warp = t >> 5;
    size_t base = (size_t)blockIdx.x * SEQ;
    const float4* src4 = reinterpret_cast<const float4*>(g_scores + base);

    float4 v[4];
    float mx = -3.0e38f;
    #pragma unroll
    for (int q = 0; q < 4; q++) {
        v[q] = src4[t + 256*q];
        mx = fmaxf(mx, fmaxf(fmaxf(v[q].x, v[q].y), fmaxf(v[q].z, v[q].w)));
    }
    #pragma unroll
    for (int o = 16; o > 0; o >>= 1) mx = fmaxf(mx, __shfl_xor_sync(0xffffffffu, mx, o));
    if (lane == 0) red[warp] = mx;
    __syncthreads();
    if (t == 0) {
        float m = red[0];
        #pragma unroll
        for (int w = 1; w < 8; w++) m = fmaxf(m, red[w]);
        red[32] = m;
    }
    __syncthreads();
    mx = red[32];

    float sum = 0.0f;
    #pragma unroll
    for (int q = 0; q < 4; q++) {
        v[q].x = expf(v[q].x - mx);
        v[q].y = expf(v[q].y - mx);
        v[q].z = expf(v[q].z - mx);
        v[q].w = expf(v[q].w - mx);
        sum += (v[q].x + v[q].y) + (v[q].z + v[q].w);
    }
    #pragma unroll
    for (int o = 16; o > 0; o >>= 1) sum += __shfl_xor_sync(0xffffffffu, sum, o);
    if (lane == 0) red[8 + warp] = sum;
    __syncthreads();
    if (t == 0) {
        float s = 0.0f;
        #pragma unroll
        for (int w = 0; w < 8; w++) s += red[8 + w];
        red[33] = 1.0f / s;
    }
    __syncthreads();
    float inv = red[33];

    __nv_bfloat162* ph = reinterpret_cast<__nv_bfloat162*>(g_phi + base);
    __nv_bfloat162* pl = reinterpret_cast<__nv_bfloat162*>(g_plo + base);
    #pragma unroll
    for (int q = 0; q < 4; q++) {
        float p0 = v[q].x * inv, p1 = v[q].y * inv, p2 = v[q].z * inv, p3 = v[q].w * inv;
        __nv_bfloat16 h0 = __float2bfloat16(p0), h1 = __float2bfloat16(p1);
        __nv_bfloat16 h2 = __float2bfloat16(p2), h3 = __float2bfloat16(p3);
        float l0 = p0 - __bfloat162float(h0), l1 = p1 - __bfloat162float(h1);
        float l2 = p2 - __bfloat162float(h2), l3 = p3 - __bfloat162float(h3);
        int pi = 2*(t + 256*q);
        ph[pi]   = __halves2bfloat162(h0, h1);
        ph[pi+1] = __halves2bfloat162(h2, h3);
        pl[pi]   = __halves2bfloat162(__float2bfloat16(l0), __float2bfloat16(l1));
        pl[pi+1] = __halves2bfloat162(__float2bfloat16(l2), __float2bfloat16(l3));
    }
}

// ---------------- GEMM 3: Z = P @ V (NN), K = 4096, fp32 out ----------------
__global__ __launch_bounds__(256) void z_kernel(float* __restrict__ out) {
    __shared__ __nv_bfloat16 Ash[128*24];
    __shared__ __nv_bfloat16 Asl[128*24];
    __shared__ __nv_bfloat16 Bsh[16*80];
    __shared__ __nv_bfloat16 Bsl[16*80];

    const int b  = blockIdx.z;
    const int n0 = blockIdx.x * 64;
    const int i0 = blockIdx.y * 128;
    const int t  = threadIdx.x;
    const int wid = t >> 5;
    const int wm = wid >> 1, wn = wid & 1;

    const __nv_bfloat16* __restrict__ Agh = g_phi + (size_t)b*SEQ*SEQ;
    const __nv_bfloat16* __restrict__ Agl = g_plo + (size_t)b*SEQ*SEQ;
    const __nv_bfloat16* __restrict__ Bgh = g_vhi + (size_t)b*SEQ*DIM;
    const __nv_bfloat16* __restrict__ Bgl = g_vlo + (size_t)b*SEQ*DIM;

    wmma::fragment<wmma::accumulator,16,16,16,float> acc[2][2];
    #pragma unroll
    for (int mi=0; mi<2; mi++)
        #pragma unroll
        for (int ni=0; ni<2; ni++)
            wmma::fill_fragment(acc[mi][ni], 0.0f);

    const int arow = t >> 1, aseg = t & 1;
    const int brow = t >> 3, bseg = t & 7;
    const bool bact = (t < 128);

    uint4 rAh, rAl, rBh, rBl;
    rAh = *reinterpret_cast<const uint4*>(Agh + (size_t)(i0+arow)*SEQ + aseg*8);
    rAl = *reinterpret_cast<const uint4*>(Agl + (size_t)(i0+arow)*SEQ + aseg*8);
    if (bact) {
        rBh = *reinterpret_cast<const uint4*>(Bgh + (size_t)brow*DIM + n0 + bseg*8);
        rBl = *reinterpret_cast<const uint4*>(Bgl + (size_t)brow*DIM + n0 + bseg*8);
    }

    const int KSTEPS = SEQ/16;
    for (int kt = 0; kt < KSTEPS; kt++) {
        *reinterpret_cast<uint4*>(&Ash[arow*24 + aseg*8]) = rAh;
        *reinterpret_cast<uint4*>(&Asl[arow*24 + aseg*8]) = rAl;
        if (bact) {
            *reinterpret_cast<uint4*>(&Bsh[brow*80 + bseg*8]) = rBh;
            *reinterpret_cast<uint4*>(&Bsl[brow*80 + bseg*8]) = rBl;
        }
        __syncthreads();
        if (kt+1 < KSTEPS) {
            int k0 = (kt+1)*16;
            rAh = *reinterpret_cast<const uint4*>(Agh + (size_t)(i0+arow)*SEQ + k0 + aseg*8);
            rAl = *reinterpret_cast<const uint4*>(Agl + (size_t)(i0+arow)*SEQ + k0 + aseg*8);
            if (bact) {
                rBh = *reinterpret_cast<const uint4*>(Bgh + (size_t)(k0+brow)*DIM + n0 + bseg*8);
                rBl = *reinterpret_cast<const uint4*>(Bgl + (size_t)(k0+brow)*DIM + n0 + bseg*8);
            }
        }
        wmma::fragment<wmma::matrix_a,16,16,16,__nv_bfloat16,wmma::row_major> fah[2], fal[2];
        wmma::fragment<wmma::matrix_b,16,16,16,__nv_bfloat16,wmma::row_major> fbh[2], fbl[2];
        #pragma unroll
        for (int mi=0; mi<2; mi++) {
            wmma::load_matrix_sync(fah[mi], &Ash[(wm*32+mi*16)*24], 24);
            wmma::load_matrix_sync(fal[mi], &Asl[(wm*32+mi*16)*24], 24);
        }
        #pragma unroll
        for (int ni=0; ni<2; ni++) {
            wmma::load_matrix_sync(fbh[ni], &Bsh[wn*32+ni*16], 80);
            wmma::load_matrix_sync(fbl[ni], &Bsl[wn*32+ni*16], 80);
        }
        #pragma unroll
        for (int mi=0; mi<2; mi++)
            #pragma unroll
            for (int ni=0; ni<2; ni++) {
                wmma::mma_sync(acc[mi][ni], fah[mi], fbh[ni], acc[mi][ni]);
                wmma::mma_sync(acc[mi][ni], fah[mi], fbl[ni], acc[mi][ni]);
                wmma::mma_sync(acc[mi][ni], fal[mi], fbh[ni], acc[mi][ni]);
            }
        __syncthreads();
    }

    #pragma unroll
    for (int mi=0; mi<2; mi++)
        #pragma unroll
        for (int ni=0; ni<2; ni++) {
            float* Cp = out + (size_t)b*SEQ*DIM
                        + (size_t)(i0 + wm*32 + mi*16)*DIM + (n0 + wn*32 + ni*16);
            wmma::store_matrix_sync(Cp, acc[mi][ni], DIM, wmma::mem_row_major);
        }
}

// ---------------- launch ----------------
extern "C" void kernel_launch(void* const* d_in, const int* in_sizes, int n_in,
                              void* d_out, int out_size) {
    (void)in_sizes; (void)n_in; (void)out_size;
    const float* x  = (const float*)d_in[0];
    const float* Wq = (const float*)d_in[1];
    const float* bq = (const float*)d_in[2];
    const float* Wk = (const float*)d_in[3];
    const float* bk = (const float*)d_in[4];
    const float* Wv = (const float*)d_in[5];
    const float* bv = (const float*)d_in[6];
    float* out = (float*)d_out;

    const int nx2 = NTOK*DIM/2;
    const int nw2 = DIM*DIM/2;
    split_kernel<<<(nx2 + 255)/256, 256>>>(x,  0, nx2);
    split_kernel<<<(nw2 + 255)/256, 256>>>(Wq, 1, nw2);
    split_kernel<<<(nw2 + 255)/256, 256>>>(Wk, 2, nw2);
    split_kernel<<<(nw2 + 255)/256, 256>>>(Wv, 3, nw2);

    qkv_kernel<<<dim3(DIM/64, NTOK/128, 3), 256>>>(bq, bk, bv);
    scores_kernel<<<dim3(SEQ/64, SEQ/128, BATCH), 256>>>();
    softmax_kernel<<<NTOK, 256>>>();
    z_kernel<<<dim3(DIM/64, SEQ/128, BATCH), 256>>>(out);
}

// round 13
// speedup vs baseline: 1.5059x; 1.5049x over previous
#include <cuda_runtime.h>
#include <cuda_bf16.h>
#include <mma.h>

using namespace nvcuda;

#define BATCH 4
#define SEQ   4096
#define DIM   512
#define NTOK  (BATCH*SEQ)

// ---------------- scratch (__device__ globals; no allocations anywhere) ----------------
__device__ __nv_bfloat16 g_xhi[NTOK*DIM];
__device__ __nv_bfloat16 g_xlo[NTOK*DIM];
__device__ __nv_bfloat16 g_whi[3*DIM*DIM];
__device__ __nv_bfloat16 g_wlo[3*DIM*DIM];
__device__ __nv_bfloat16 g_qhi[NTOK*DIM];
__device__ __nv_bfloat16 g_qlo[NTOK*DIM];
__device__ __nv_bfloat16 g_khi[NTOK*DIM];
__device__ __nv_bfloat16 g_klo[NTOK*DIM];
__device__ __nv_bfloat16 g_vhi[NTOK*DIM];
__device__ __nv_bfloat16 g_vlo[NTOK*DIM];
__device__ float         g_scores[(size_t)BATCH*SEQ*SEQ];
__device__ __nv_bfloat16 g_phi[(size_t)BATCH*SEQ*SEQ];
__device__ __nv_bfloat16 g_plo[(size_t)BATCH*SEQ*SEQ];

// ---------------- cp.async helpers ----------------
__device__ __forceinline__ void cp16(void* dst, const void* src) {
    unsigned sa = (unsigned)__cvta_generic_to_shared(dst);
    asm volatile("cp.async.cg.shared.global [%0], [%1], 16;\n" :: "r"(sa), "l"(src));
}
__device__ __forceinline__ void cp_commit() {
    asm volatile("cp.async.commit_group;\n" ::: "memory");
}
__device__ __forceinline__ void cp_wait0() {
    asm volatile("cp.async.wait_group 0;\n" ::: "memory");
}

// ---------------- fp32 -> bf16 hi/lo split ----------------
__global__ __launch_bounds__(256) void split_kernel(const float* __restrict__ src,
                                                    int which, int n2) {
    int i = blockIdx.x * 256 + threadIdx.x;
    if (i >= n2) return;
    __nv_bfloat16 *hi, *lo;
    if (which == 0) { hi = g_xhi; lo = g_xlo; }
    else            { hi = g_whi + (which-1)*DIM*DIM; lo = g_wlo + (which-1)*DIM*DIM; }
    float2 v = reinterpret_cast<const float2*>(src)[i];
    __nv_bfloat16 h0 = __float2bfloat16(v.x);
    __nv_bfloat16 h1 = __float2bfloat16(v.y);
    float l0 = v.x - __bfloat162float(h0);
    float l1 = v.y - __bfloat162float(h1);
    reinterpret_cast<__nv_bfloat162*>(hi)[i] = __halves2bfloat162(h0, h1);
    reinterpret_cast<__nv_bfloat162*>(lo)[i] =
        __halves2bfloat162(__float2bfloat16(l0), __float2bfloat16(l1));
}

// =====================================================================================
// GEMM 1: QKV projection (NN). C[NTOK,DIM] = X @ W + bias, 128x128 blocks, cp.async.
// =====================================================================================
__global__ __launch_bounds__(256) void qkv_kernel(const float* __restrict__ bq,
                                                  const float* __restrict__ bk,
                                                  const float* __restrict__ bv) {
    __shared__ __nv_bfloat16 Ah[2][128*24], Al[2][128*24];
    __shared__ __nv_bfloat16 Bh[2][16*136], Bl[2][16*136];

    const int z  = blockIdx.z;
    const int n0 = blockIdx.x * 128;
    const int i0 = blockIdx.y * 128;
    const int t  = threadIdx.x;
    const int wid = t >> 5, lane = t & 31;
    const int wm = wid >> 1, wn = wid & 1;           // 4x2 warp grid, warp tile 32x64

    const __nv_bfloat16* __restrict__ Agh = g_xhi;
    const __nv_bfloat16* __restrict__ Agl = g_xlo;
    const __nv_bfloat16* __restrict__ Bgh = g_whi + z*DIM*DIM;
    const __nv_bfloat16* __restrict__ Bgl = g_wlo + z*DIM*DIM;
    const float* bias = (z==0) ? bq : (z==1) ? bk : bv;
    __nv_bfloat16* Oh = (z==0) ? g_qhi : (z==1) ? g_khi : g_vhi;
    __nv_bfloat16* Ol = (z==0) ? g_qlo : (z==1) ? g_klo : g_vlo;

    wmma::fragment<wmma::accumulator,16,16,16,float> acc[2][4];
    #pragma unroll
    for (int mi=0; mi<2; mi++)
        #pragma unroll
        for (int ni=0; ni<4; ni++)
            wmma::fill_fragment(acc[mi][ni], 0.0f);

    const int arow = t >> 1, aseg = t & 1;           // A: 128 rows x 2 chunks of 8 bf16
    const int brow = t >> 4, bseg = t & 15;          // B: 16 rows x 16 chunks

    auto load_stage = [&](int kt, int s) {
        int k0 = kt * 16;
        cp16(&Ah[s][arow*24 + aseg*8], Agh + (size_t)(i0+arow)*DIM + k0 + aseg*8);
        cp16(&Al[s][arow*24 + aseg*8], Agl + (size_t)(i0+arow)*DIM + k0 + aseg*8);
        cp16(&Bh[s][brow*136 + bseg*8], Bgh + (size_t)(k0+brow)*DIM + n0 + bseg*8);
        cp16(&Bl[s][brow*136 + bseg*8], Bgl + (size_t)(k0+brow)*DIM + n0 + bseg*8);
        cp_commit();
    };

    const int KSTEPS = DIM/16;
    load_stage(0, 0);
    for (int kt = 0; kt < KSTEPS; kt++) {
        cp_wait0();
        __syncthreads();
        const int cur = kt & 1;
        if (kt+1 < KSTEPS) load_stage(kt+1, cur^1);

        wmma::fragment<wmma::matrix_a,16,16,16,__nv_bfloat16,wmma::row_major> fah[2], fal[2];
        wmma::fragment<wmma::matrix_b,16,16,16,__nv_bfloat16,wmma::row_major> fbh[4], fbl[4];
        #pragma unroll
        for (int mi=0; mi<2; mi++) {
            wmma::load_matrix_sync(fah[mi], &Ah[cur][(wm*32+mi*16)*24], 24);
            wmma::load_matrix_sync(fal[mi], &Al[cur][(wm*32+mi*16)*24], 24);
        }
        #pragma unroll
        for (int ni=0; ni<4; ni++) {
            wmma::load_matrix_sync(fbh[ni], &Bh[cur][wn*64+ni*16], 136);
            wmma::load_matrix_sync(fbl[ni], &Bl[cur][wn*64+ni*16], 136);
        }
        #pragma unroll
        for (int mi=0; mi<2; mi++)
            #pragma unroll
            for (int ni=0; ni<4; ni++) {
                wmma::mma_sync(acc[mi][ni], fah[mi], fbh[ni], acc[mi][ni]);
                wmma::mma_sync(acc[mi][ni], fah[mi], fbl[ni], acc[mi][ni]);
                wmma::mma_sync(acc[mi][ni], fal[mi], fbh[ni], acc[mi][ni]);
            }
    }

    // epilogue: stage each 16x16 fragment (reusing Ah smem), add bias, split to hi/lo
    __syncthreads();
    float* buf = reinterpret_cast<float*>(&Ah[0][0]) + wid * (16*20);
    #pragma unroll
    for (int mi=0; mi<2; mi++)
        #pragma unroll
        for (int ni=0; ni<4; ni++) {
            wmma::store_matrix_sync(buf, acc[mi][ni], 20, wmma::mem_row_major);
            __syncwarp();
            int gi = i0 + wm*32 + mi*16;
            int gn = n0 + wn*64 + ni*16;
            for (int e = lane; e < 256; e += 32) {
                int r = e >> 4, c = e & 15;
                float v = buf[r*20 + c] + bias[gn + c];
                __nv_bfloat16 h = __float2bfloat16(v);
                float l = v - __bfloat162float(h);
                size_t off = (size_t)(gi + r)*DIM + gn + c;
                Oh[off] = h;
                Ol[off] = __float2bfloat16(l);
            }
            __syncwarp();
        }
}

// =====================================================================================
// GEMM 2: scores = Q @ K^T * 0.5 (NT). 128x128 blocks, cp.async, fp32 out.
// =====================================================================================
__global__ __launch_bounds__(256) void scores_kernel() {
    __shared__ __nv_bfloat16 Ah[2][128*24], Al[2][128*24];
    __shared__ __nv_bfloat16 Bh[2][128*24], Bl[2][128*24];   // K-rows tile (NT)

    const int b  = blockIdx.z;
    const int j0 = blockIdx.x * 128;
    const int i0 = blockIdx.y * 128;
    const int t  = threadIdx.x;
    const int wid = t >> 5;
    const int wm = wid >> 1, wn = wid & 1;

    const __nv_bfloat16* __restrict__ Agh = g_qhi + (size_t)b*SEQ*DIM;
    const __nv_bfloat16* __restrict__ Agl = g_qlo + (size_t)b*SEQ*DIM;
    const __nv_bfloat16* __restrict__ Bgh = g_khi + (size_t)b*SEQ*DIM;
    const __nv_bfloat16* __restrict__ Bgl = g_klo + (size_t)b*SEQ*DIM;

    wmma::fragment<wmma::accumulator,16,16,16,float> acc[2][4];
    #pragma unroll
    for (int mi=0; mi<2; mi++)
        #pragma unroll
        for (int ni=0; ni<4; ni++)
            wmma::fill_fragment(acc[mi][ni], 0.0f);

    const int arow = t >> 1, aseg = t & 1;   // both tiles: 128 rows x 2 chunks

    auto load_stage = [&](int kt, int s) {
        int k0 = kt * 16;
        cp16(&Ah[s][arow*24 + aseg*8], Agh + (size_t)(i0+arow)*DIM + k0 + aseg*8);
        cp16(&Al[s][arow*24 + aseg*8], Agl + (size_t)(i0+arow)*DIM + k0 + aseg*8);
        cp16(&Bh[s][arow*24 + aseg*8], Bgh + (size_t)(j0+arow)*DIM + k0 + aseg*8);
        cp16(&Bl[s][arow*24 + aseg*8], Bgl + (size_t)(j0+arow)*DIM + k0 + aseg*8);
        cp_commit();
    };

    const int KSTEPS = DIM/16;
    load_stage(0, 0);
    for (int kt = 0; kt < KSTEPS; kt++) {
        cp_wait0();
        __syncthreads();
        const int cur = kt & 1;
        if (kt+1 < KSTEPS) load_stage(kt+1, cur^1);

        wmma::fragment<wmma::matrix_a,16,16,16,__nv_bfloat16,wmma::row_major> fah[2], fal[2];
        wmma::fragment<wmma::matrix_b,16,16,16,__nv_bfloat16,wmma::col_major> fbh[4], fbl[4];
        #pragma unroll
        for (int mi=0; mi<2; mi++) {
            wmma::load_matrix_sync(fah[mi], &Ah[cur][(wm*32+mi*16)*24], 24);
            wmma::load_matrix_sync(fal[mi], &Al[cur][(wm*32+mi*16)*24], 24);
        }
        #pragma unroll
        for (int ni=0; ni<4; ni++) {
            wmma::load_matrix_sync(fbh[ni], &Bh[cur][(wn*64+ni*16)*24], 24);
            wmma::load_matrix_sync(fbl[ni], &Bl[cur][(wn*64+ni*16)*24], 24);
        }
        #pragma unroll
        for (int mi=0; mi<2; mi++)
            #pragma unroll
            for (int ni=0; ni<4; ni++) {
                wmma::mma_sync(acc[mi][ni], fah[mi], fbh[ni], acc[mi][ni]);
                wmma::mma_sync(acc[mi][ni], fah[mi], fbl[ni], acc[mi][ni]);
                wmma::mma_sync(acc[mi][ni], fal[mi], fbh[ni], acc[mi][ni]);
            }
    }

    #pragma unroll
    for (int mi=0; mi<2; mi++)
        #pragma unroll
        for (int ni=0; ni<4; ni++) {
            #pragma unroll
            for (int e = 0; e < acc[mi][ni].num_elements; e++)
                acc[mi][ni].x[e] *= 0.5f;    // scale = batch/2 = 2 -> divide by 2
            float* Cp = g_scores + (size_t)b*SEQ*SEQ
                        + (size_t)(i0 + wm*32 + mi*16)*SEQ + (j0 + wn*64 + ni*16);
            wmma::store_matrix_sync(Cp, acc[mi][ni], SEQ, wmma::mem_row_major);
        }
}

// ---------------- softmax over rows of 4096, writes P as bf16 hi/lo ----------------
__global__ __launch_bounds__(256) void softmax_kernel() {
    __shared__ float red[40];
    const int t = threadIdx.x;
    const int lane = t & 31, warp = t >> 5;
    size_t base = (size_t)blockIdx.x * SEQ;
    const float4* src4 = reinterpret_cast<const float4*>(g_scores + base);

    float4 v[4];
    float mx = -3.0e38f;
    #pragma unroll
    for (int q = 0; q < 4; q++) {
        v[q] = src4[t + 256*q];
        mx = fmaxf(mx, fmaxf(fmaxf(v[q].x, v[q].y), fmaxf(v[q].z, v[q].w)));
    }
    #pragma unroll
    for (int o = 16; o > 0; o >>= 1) mx = fmaxf(mx, __shfl_xor_sync(0xffffffffu, mx, o));
    if (lane == 0) red[warp] = mx;
    __syncthreads();
    if (t == 0) {
        float m = red[0];
        #pragma unroll
        for (int w = 1; w < 8; w++) m = fmaxf(m, red[w]);
        red[32] = m;
    }
    __syncthreads();
    mx = red[32];

    float sum = 0.0f;
    #pragma unroll
    for (int q = 0; q < 4; q++) {
        v[q].x = expf(v[q].x - mx);
        v[q].y = expf(v[q].y - mx);
        v[q].z = expf(v[q].z - mx);
        v[q].w = expf(v[q].w - mx);
        sum += (v[q].x + v[q].y) + (v[q].z + v[q].w);
    }
    #pragma unroll
    for (int o = 16; o > 0; o >>= 1) sum += __shfl_xor_sync(0xffffffffu, sum, o);
    if (lane == 0) red[8 + warp] = sum;
    __syncthreads();
    if (t == 0) {
        float s = 0.0f;
        #pragma unroll
        for (int w = 0; w < 8; w++) s += red[8 + w];
        red[33] = 1.0f / s;
    }
    __syncthreads();
    float inv = red[33];

    __nv_bfloat162* ph = reinterpret_cast<__nv_bfloat162*>(g_phi + base);
    __nv_bfloat162* pl = reinterpret_cast<__nv_bfloat162*>(g_plo + base);
    #pragma unroll
    for (int q = 0; q < 4; q++) {
        float p0 = v[q].x * inv, p1 = v[q].y * inv, p2 = v[q].z * inv, p3 = v[q].w * inv;
        __nv_bfloat16 h0 = __float2bfloat16(p0), h1 = __float2bfloat16(p1);
        __nv_bfloat16 h2 = __float2bfloat16(p2), h3 = __float2bfloat16(p3);
        float l0 = p0 - __bfloat162float(h0), l1 = p1 - __bfloat162float(h1);
        float l2 = p2 - __bfloat162float(h2), l3 = p3 - __bfloat162float(h3);
        int pi = 2*(t + 256*q);
        ph[pi]   = __halves2bfloat162(h0, h1);
        ph[pi+1] = __halves2bfloat162(h2, h3);
        pl[pi]   = __halves2bfloat162(__float2bfloat16(l0), __float2bfloat16(l1));
        pl[pi+1] = __halves2bfloat162(__float2bfloat16(l2), __float2bfloat16(l3));
    }
}

// =====================================================================================
// GEMM 3: Z = P @ V (NN), K = 4096. 128x128 blocks, cp.async, fp32 out.
// =====================================================================================
__global__ __launch_bounds__(256) void z_kernel(float* __restrict__ out) {
    __shared__ __nv_bfloat16 Ah[2][128*24], Al[2][128*24];
    __shared__ __nv_bfloat16 Bh[2][16*136], Bl[2][16*136];

    const int b  = blockIdx.z;
    const int n0 = blockIdx.x * 128;
    const int i0 = blockIdx.y * 128;
    const int t  = threadIdx.x;
    const int wid = t >> 5;
    const int wm = wid >> 1, wn = wid & 1;

    const __nv_bfloat16* __restrict__ Agh = g_phi + (size_t)b*SEQ*SEQ;
    const __nv_bfloat16* __restrict__ Agl = g_plo + (size_t)b*SEQ*SEQ;
    const __nv_bfloat16* __restrict__ Bgh = g_vhi + (size_t)b*SEQ*DIM;
    const __nv_bfloat16* __restrict__ Bgl = g_vlo + (size_t)b*SEQ*DIM;

    wmma::fragment<wmma::accumulator,16,16,16,float> acc[2][4];
    #pragma unroll
    for (int mi=0; mi<2; mi++)
        #pragma unroll
        for (int ni=0; ni<4; ni++)
            wmma::fill_fragment(acc[mi][ni], 0.0f);

    const int arow = t >> 1, aseg = t & 1;
    const int brow = t >> 4, bseg = t & 15;

    auto load_stage = [&](int kt, int s) {
        int k0 = kt * 16;
        cp16(&Ah[s][arow*24 + aseg*8], Agh + (size_t)(i0+arow)*SEQ + k0 + aseg*8);
        cp16(&Al[s][arow*24 + aseg*8], Agl + (size_t)(i0+arow)*SEQ + k0 + aseg*8);
        cp16(&Bh[s][brow*136 + bseg*8], Bgh + (size_t)(k0+brow)*DIM + n0 + bseg*8);
        cp16(&Bl[s][brow*136 + bseg*8], Bgl + (size_t)(k0+brow)*DIM + n0 + bseg*8);
        cp_commit();
    };

    const int KSTEPS = SEQ/16;
    load_stage(0, 0);
    for (int kt = 0; kt < KSTEPS; kt++) {
        cp_wait0();
        __syncthreads();
        const int cur = kt & 1;
        if (kt+1 < KSTEPS) load_stage(kt+1, cur^1);

        wmma::fragment<wmma::matrix_a,16,16,16,__nv_bfloat16,wmma::row_major> fah[2], fal[2];
        wmma::fragment<wmma::matrix_b,16,16,16,__nv_bfloat16,wmma::row_major> fbh[4], fbl[4];
        #pragma unroll
        for (int mi=0; mi<2; mi++) {
            wmma::load_matrix_sync(fah[mi], &Ah[cur][(wm*32+mi*16)*24], 24);
            wmma::load_matrix_sync(fal[mi], &Al[cur][(wm*32+mi*16)*24], 24);
        }
        #pragma unroll
        for (int ni=0; ni<4; ni++) {
            wmma::load_matrix_sync(fbh[ni], &Bh[cur][wn*64+ni*16], 136);
            wmma::load_matrix_sync(fbl[ni], &Bl[cur][wn*64+ni*16], 136);
        }
        #pragma unroll
        for (int mi=0; mi<2; mi++)
            #pragma unroll
            for (int ni=0; ni<4; ni++) {
                wmma::mma_sync(acc[mi][ni], fah[mi], fbh[ni], acc[mi][ni]);
                wmma::mma_sync(acc[mi][ni], fah[mi], fbl[ni], acc[mi][ni]);
                wmma::mma_sync(acc[mi][ni], fal[mi], fbh[ni], acc[mi][ni]);
            }
    }

    #pragma unroll
    for (int mi=0; mi<2; mi++)
        #pragma unroll
        for (int ni=0; ni<4; ni++) {
            float* Cp = out + (size_t)b*SEQ*DIM
                        + (size_t)(i0 + wm*32 + mi*16)*DIM + (n0 + wn*64 + ni*16);
            wmma::store_matrix_sync(Cp, acc[mi][ni], DIM, wmma::mem_row_major);
        }
}

// ---------------- launch ----------------
extern "C" void kernel_launch(void* const* d_in, const int* in_sizes, int n_in,
                              void* d_out, int out_size) {
    (void)in_sizes; (void)n_in; (void)out_size;
    const float* x  = (const float*)d_in[0];
    const float* Wq = (const float*)d_in[1];
    const float* bq = (const float*)d_in[2];
    const float* Wk = (const float*)d_in[3];
    const float* bk = (const float*)d_in[4];
    const float* Wv = (const float*)d_in[5];
    const float* bv = (const float*)d_in[6];
    float* out = (float*)d_out;

    const int nx2 = NTOK*DIM/2;
    const int nw2 = DIM*DIM/2;
    split_kernel<<<(nx2 + 255)/256, 256>>>(x,  0, nx2);
    split_kernel<<<(nw2 + 255)/256, 256>>>(Wq, 1, nw2);
    split_kernel<<<(nw2 + 255)/256, 256>>>(Wk, 2, nw2);
    split_kernel<<<(nw2 + 255)/256, 256>>>(Wv, 3, nw2);

    qkv_kernel<<<dim3(DIM/128, NTOK/128, 3), 256>>>(bq, bk, bv);
    scores_kernel<<<dim3(SEQ/128, SEQ/128, BATCH), 256>>>();
    softmax_kernel<<<NTOK, 256>>>();
    z_kernel<<<dim3(DIM/128, SEQ/128, BATCH), 256>>>(out);
}

// round 15
// speedup vs baseline: 1.8051x; 1.1987x over previous
#include <cuda_runtime.h>
#include <cuda_fp16.h>
#include <mma.h>

using namespace nvcuda;

#define BATCH 4
#define SEQ   4096
#define DIM   512
#define NTOK  (BATCH*SEQ)

// ---------------- scratch (__device__ globals; no allocations anywhere) ----------------
__device__ __half g_xhi[NTOK*DIM];
__device__ __half g_xlo[NTOK*DIM];
__device__ __half g_whi[3*DIM*DIM];
__device__ __half g_wlo[3*DIM*DIM];
__device__ __half g_qhi[NTOK*DIM];
__device__ __half g_qlo[NTOK*DIM];
__device__ __half g_khi[NTOK*DIM];
__device__ __half g_klo[NTOK*DIM];
__device__ __half g_vhi[NTOK*DIM];
__device__ __half g_vlo[NTOK*DIM];
__device__ float  g_scores[(size_t)BATCH*SEQ*SEQ];
__device__ __half g_p[(size_t)BATCH*SEQ*SEQ];

// ---------------- cp.async helpers ----------------
__device__ __forceinline__ void cp16(void* dst, const void* src) {
    unsigned sa = (unsigned)__cvta_generic_to_shared(dst);
    asm volatile("cp.async.cg.shared.global [%0], [%1], 16;\n" :: "r"(sa), "l"(src));
}
__device__ __forceinline__ void cp_commit() {
    asm volatile("cp.async.commit_group;\n" ::: "memory");
}
__device__ __forceinline__ void cp_wait0() {
    asm volatile("cp.async.wait_group 0;\n" ::: "memory");
}

// ---------------- fp32 -> fp16 hi/lo split ----------------
__global__ __launch_bounds__(256) void split_kernel(const float* __restrict__ src,
                                                    int which, int n2) {
    int i = blockIdx.x * 256 + threadIdx.x;
    if (i >= n2) return;
    __half *hi, *lo;
    if (which == 0) { hi = g_xhi; lo = g_xlo; }
    else            { hi = g_whi + (which-1)*DIM*DIM; lo = g_wlo + (which-1)*DIM*DIM; }
    float2 v = reinterpret_cast<const float2*>(src)[i];
    __half h0 = __float2half(v.x);
    __half h1 = __float2half(v.y);
    float l0 = v.x - __half2float(h0);
    float l1 = v.y - __half2float(h1);
    reinterpret_cast<__half2*>(hi)[i] = __halves2half2(h0, h1);
    reinterpret_cast<__half2*>(lo)[i] =
        __halves2half2(__float2half(l0), __float2half(l1));
}

// =====================================================================================
// GEMM 1: QKV projection (NN). C[NTOK,DIM] = X @ W + bias, 128x128 blocks, cp.async.
// 3-term fp16 split: hh + hl + lh.
// =====================================================================================
__global__ __launch_bounds__(256) void qkv_kernel(const float* __restrict__ bq,
                                                  const float* __restrict__ bk,
                                                  const float* __restrict__ bv) {
    __shared__ __half Ah[2][128*24], Al[2][128*24];
    __shared__ __half Bh[2][16*136], Bl[2][16*136];

    const int z  = blockIdx.z;
    const int n0 = blockIdx.x * 128;
    const int i0 = blockIdx.y * 128;
    const int t  = threadIdx.x;
    const int wid = t >> 5, lane = t & 31;
    const int wm = wid >> 1, wn = wid & 1;           // 4x2 warp grid, warp tile 32x64

    const __half* __restrict__ Agh = g_xhi;
    const __half* __restrict__ Agl = g_xlo;
    const __half* __restrict__ Bgh = g_whi + z*DIM*DIM;
    const __half* __restrict__ Bgl = g_wlo + z*DIM*DIM;
    const float* bias = (z==0) ? bq : (z==1) ? bk : bv;
    __half* Oh = (z==0) ? g_qhi : (z==1) ? g_khi : g_vhi;
    __half* Ol = (z==0) ? g_qlo : (z==1) ? g_klo : g_vlo;

    wmma::fragment<wmma::accumulator,16,16,16,float> acc[2][4];
    #pragma unroll
    for (int mi=0; mi<2; mi++)
        #pragma unroll
        for (int ni=0; ni<4; ni++)
            wmma::fill_fragment(acc[mi][ni], 0.0f);

    const int arow = t >> 1, aseg = t & 1;           // A: 128 rows x 2 chunks of 8
    const int brow = t >> 4, bseg = t & 15;          // B: 16 rows x 16 chunks

    auto load_stage = [&](int kt, int s) {
        int k0 = kt * 16;
        cp16(&Ah[s][arow*24 + aseg*8], Agh + (size_t)(i0+arow)*DIM + k0 + aseg*8);
        cp16(&Al[s][arow*24 + aseg*8], Agl + (size_t)(i0+arow)*DIM + k0 + aseg*8);
        cp16(&Bh[s][brow*136 + bseg*8], Bgh + (size_t)(k0+brow)*DIM + n0 + bseg*8);
        cp16(&Bl[s][brow*136 + bseg*8], Bgl + (size_t)(k0+brow)*DIM + n0 + bseg*8);
        cp_commit();
    };

    const int KSTEPS = DIM/16;
    load_stage(0, 0);
    for (int kt = 0; kt < KSTEPS; kt++) {
        cp_wait0();
        __syncthreads();
        const int cur = kt & 1;
        if (kt+1 < KSTEPS) load_stage(kt+1, cur^1);

        wmma::fragment<wmma::matrix_a,16,16,16,__half,wmma::row_major> fah[2], fal[2];
        wmma::fragment<wmma::matrix_b,16,16,16,__half,wmma::row_major> fbh[4], fbl[4];
        #pragma unroll
        for (int mi=0; mi<2; mi++) {
            wmma::load_matrix_sync(fah[mi], &Ah[cur][(wm*32+mi*16)*24], 24);
            wmma::load_matrix_sync(fal[mi], &Al[cur][(wm*32+mi*16)*24], 24);
        }
        #pragma unroll
        for (int ni=0; ni<4; ni++) {
            wmma::load_matrix_sync(fbh[ni], &Bh[cur][wn*64+ni*16], 136);
            wmma::load_matrix_sync(fbl[ni], &Bl[cur][wn*64+ni*16], 136);
        }
        #pragma unroll
        for (int mi=0; mi<2; mi++)
            #pragma unroll
            for (int ni=0; ni<4; ni++) {
                wmma::mma_sync(acc[mi][ni], fah[mi], fbh[ni], acc[mi][ni]);
                wmma::mma_sync(acc[mi][ni], fah[mi], fbl[ni], acc[mi][ni]);
                wmma::mma_sync(acc[mi][ni], fal[mi], fbh[ni], acc[mi][ni]);
            }
    }

    // epilogue: stage each 16x16 fragment (reusing Ah smem), add bias, split to hi/lo
    __syncthreads();
    float* buf = reinterpret_cast<float*>(&Ah[0][0]) + wid * (16*20);
    #pragma unroll
    for (int mi=0; mi<2; mi++)
        #pragma unroll
        for (int ni=0; ni<4; ni++) {
            wmma::store_matrix_sync(buf, acc[mi][ni], 20, wmma::mem_row_major);
            __syncwarp();
            int gi = i0 + wm*32 + mi*16;
            int gn = n0 + wn*64 + ni*16;
            for (int e = lane; e < 256; e += 32) {
                int r = e >> 4, c = e & 15;
                float v = buf[r*20 + c] + bias[gn + c];
                __half h = __float2half(v);
                float l = v - __half2float(h);
                size_t off = (size_t)(gi + r)*DIM + gn + c;
                Oh[off] = h;
                Ol[off] = __float2half(l);
            }
            __syncwarp();
        }
}

// =====================================================================================
// GEMM 2: scores = Q @ K^T * 0.5 (NT). 128x128 blocks, cp.async, fp32 out. 3-term.
// =====================================================================================
__global__ __launch_bounds__(256) void scores_kernel() {
    __shared__ __half Ah[2][128*24], Al[2][128*24];
    __shared__ __half Bh[2][128*24], Bl[2][128*24];

    const int b  = blockIdx.z;
    const int j0 = blockIdx.x * 128;
    const int i0 = blockIdx.y * 128;
    const int t  = threadIdx.x;
    const int wid = t >> 5;
    const int wm = wid >> 1, wn = wid & 1;

    const __half* __restrict__ Agh = g_qhi + (size_t)b*SEQ*DIM;
    const __half* __restrict__ Agl = g_qlo + (size_t)b*SEQ*DIM;
    const __half* __restrict__ Bgh = g_khi + (size_t)b*SEQ*DIM;
    const __half* __restrict__ Bgl = g_klo + (size_t)b*SEQ*DIM;

    wmma::fragment<wmma::accumulator,16,16,16,float> acc[2][4];
    #pragma unroll
    for (int mi=0; mi<2; mi++)
        #pragma unroll
        for (int ni=0; ni<4; ni++)
            wmma::fill_fragment(acc[mi][ni], 0.0f);

    const int arow = t >> 1, aseg = t & 1;   // both tiles: 128 rows x 2 chunks

    auto load_stage = [&](int kt, int s) {
        int k0 = kt * 16;
        cp16(&Ah[s][arow*24 + aseg*8], Agh + (size_t)(i0+arow)*DIM + k0 + aseg*8);
        cp16(&Al[s][arow*24 + aseg*8], Agl + (size_t)(i0+arow)*DIM + k0 + aseg*8);
        cp16(&Bh[s][arow*24 + aseg*8], Bgh + (size_t)(j0+arow)*DIM + k0 + aseg*8);
        cp16(&Bl[s][arow*24 + aseg*8], Bgl + (size_t)(j0+arow)*DIM + k0 + aseg*8);
        cp_commit();
    };

    const int KSTEPS = DIM/16;
    load_stage(0, 0);
    for (int kt = 0; kt < KSTEPS; kt++) {
        cp_wait0();
        __syncthreads();
        const int cur = kt & 1;
        if (kt+1 < KSTEPS) load_stage(kt+1, cur^1);

        wmma::fragment<wmma::matrix_a,16,16,16,__half,wmma::row_major> fah[2], fal[2];
        wmma::fragment<wmma::matrix_b,16,16,16,__half,wmma::col_major> fbh[4], fbl[4];
        #pragma unroll
        for (int mi=0; mi<2; mi++) {
            wmma::load_matrix_sync(fah[mi], &Ah[cur][(wm*32+mi*16)*24], 24);
            wmma::load_matrix_sync(fal[mi], &Al[cur][(wm*32+mi*16)*24], 24);
        }
        #pragma unroll
        for (int ni=0; ni<4; ni++) {
            wmma::load_matrix_sync(fbh[ni], &Bh[cur][(wn*64+ni*16)*24], 24);
            wmma::load_matrix_sync(fbl[ni], &Bl[cur][(wn*64+ni*16)*24], 24);
        }
        #pragma unroll
        for (int mi=0; mi<2; mi++)
            #pragma unroll
            for (int ni=0; ni<4; ni++) {
                wmma::mma_sync(acc[mi][ni], fah[mi], fbh[ni], acc[mi][ni]);
                wmma::mma_sync(acc[mi][ni], fah[mi], fbl[ni], acc[mi][ni]);
                wmma::mma_sync(acc[mi][ni], fal[mi], fbh[ni], acc[mi][ni]);
            }
    }

    #pragma unroll
    for (int mi=0; mi<2; mi++)
        #pragma unroll
        for (int ni=0; ni<4; ni++) {
            #pragma unroll
            for (int e = 0; e < acc[mi][ni].num_elements; e++)
                acc[mi][ni].x[e] *= 0.5f;    // scale = batch/2 = 2 -> divide by 2
            float* Cp = g_scores + (size_t)b*SEQ*SEQ
                        + (size_t)(i0 + wm*32 + mi*16)*SEQ + (j0 + wn*64 + ni*16);
            wmma::store_matrix_sync(Cp, acc[mi][ni], SEQ, wmma::mem_row_major);
        }
}

// ---------------- softmax over rows of 4096, writes P as single fp16 ----------------
__global__ __launch_bounds__(256) void softmax_kernel() {
    __shared__ float red[40];
    const int t = threadIdx.x;
    const int lane = t & 31, warp = t >> 5;
    size_t base = (size_t)blockIdx.x * SEQ;
    const float4* src4 = reinterpret_cast<const float4*>(g_scores + base);

    float4 v[4];
    float mx = -3.0e38f;
    #pragma unroll
    for (int q = 0; q < 4; q++) {
        v[q] = src4[t + 256*q];
        mx = fmaxf(mx, fmaxf(fmaxf(v[q].x, v[q].y), fmaxf(v[q].z, v[q].w)));
    }
    #pragma unroll
    for (int o = 16; o > 0; o >>= 1) mx = fmaxf(mx, __shfl_xor_sync(0xffffffffu, mx, o));
    if (lane == 0) red[warp] = mx;
    __syncthreads();
    if (t == 0) {
        float m = red[0];
        #pragma unroll
        for (int w = 1; w < 8; w++) m = fmaxf(m, red[w]);
        red[32] = m;
    }
    __syncthreads();
    mx = red[32];

    float sum = 0.0f;
    #pragma unroll
    for (int q = 0; q < 4; q++) {
        v[q].x = expf(v[q].x - mx);
        v[q].y = expf(v[q].y - mx);
        v[q].z = expf(v[q].z - mx);
        v[q].w = expf(v[q].w - mx);
        sum += (v[q].x + v[q].y) + (v[q].z + v[q].w);
    }
    #pragma unroll
    for (int o = 16; o > 0; o >>= 1) sum += __shfl_xor_sync(0xffffffffu, sum, o);
    if (lane == 0) red[8 + warp] = sum;
    __syncthreads();
    if (t == 0) {
        float s = 0.0f;
        #pragma unroll
        for (int w = 0; w < 8; w++) s += red[8 + w];
        red[33] = 1.0f / s;
    }
    __syncthreads();
    float inv = red[33];

    __half2* ph = reinterpret_cast<__half2*>(g_p + base);
    #pragma unroll
    for (int q = 0; q < 4; q++) {
        float p0 = v[q].x * inv, p1 = v[q].y * inv, p2 = v[q].z * inv, p3 = v[q].w * inv;
        int pi = 2*(t + 256*q);
        ph[pi]   = __floats2half2_rn(p0, p1);
        ph[pi+1] = __floats2half2_rn(p2, p3);
    }
}

// =====================================================================================
// GEMM 3: Z = P @ V (NN), K = 4096. 2-term: P_h*V_h + P_h*V_l (same A operand).
// =====================================================================================
__global__ __launch_bounds__(256) void z_kernel(float* __restrict__ out) {
    __shared__ __half As[2][128*24];
    __shared__ __half Bh[2][16*136], Bl[2][16*136];

    const int b  = blockIdx.z;
    const int n0 = blockIdx.x * 128;
    const int i0 = blockIdx.y * 128;
    const int t  = threadIdx.x;
    const int wid = t >> 5;
    const int wm = wid >> 1, wn = wid & 1;

    const __half* __restrict__ Ag  = g_p   + (size_t)b*SEQ*SEQ;
    const __half* __restrict__ Bgh = g_vhi + (size_t)b*SEQ*DIM;
    const __half* __restrict__ Bgl = g_vlo + (size_t)b*SEQ*DIM;

    wmma::fragment<wmma::accumulator,16,16,16,float> acc[2][4];
    #pragma unroll
    for (int mi=0; mi<2; mi++)
        #pragma unroll
        for (int ni=0; ni<4; ni++)
            wmma::fill_fragment(acc[mi][ni], 0.0f);

    const int arow = t >> 1, aseg = t & 1;   // A: 128 rows x 2 chunks
    const int brow = t >> 4, bseg = t & 15;  // B: 16 rows x 16 chunks

    auto load_stage = [&](int kt, int s) {
        int k0 = kt * 16;
        cp16(&As[s][arow*24 + aseg*8], Ag + (size_t)(i0+arow)*SEQ + k0 + aseg*8);
        cp16(&Bh[s][brow*136 + bseg*8], Bgh + (size_t)(k0+brow)*DIM + n0 + bseg*8);
        cp16(&Bl[s][brow*136 + bseg*8], Bgl + (size_t)(k0+brow)*DIM + n0 + bseg*8);
        cp_commit();
    };

    const int KSTEPS = SEQ/16;
    load_stage(0, 0);
    for (int kt = 0; kt < KSTEPS; kt++) {
        cp_wait0();
        __syncthreads();
        const int cur = kt & 1;
        if (kt+1 < KSTEPS) load_stage(kt+1, cur^1);

        wmma::fragment<wmma::matrix_a,16,16,16,__half,wmma::row_major> fa[2];
        wmma::fragment<wmma::matrix_b,16,16,16,__half,wmma::row_major> fbh[4], fbl[4];
        #pragma unroll
        for (int mi=0; mi<2; mi++)
            wmma::load_matrix_sync(fa[mi], &As[cur][(wm*32+mi*16)*24], 24);
        #pragma unroll
        for (int ni=0; ni<4; ni++) {
            wmma::load_matrix_sync(fbh[ni], &Bh[cur][wn*64+ni*16], 136);
            wmma::load_matrix_sync(fbl[ni], &Bl[cur][wn*64+ni*16], 136);
        }
        #pragma unroll
        for (int mi=0; mi<2; mi++)
            #pragma unroll
            for (int ni=0; ni<4; ni++) {
                wmma::mma_sync(acc[mi][ni], fa[mi], fbh[ni], acc[mi][ni]);
                wmma::mma_sync(acc[mi][ni], fa[mi], fbl[ni], acc[mi][ni]);
            }
    }

    #pragma unroll
    for (int mi=0; mi<2; mi++)
        #pragma unroll
        for (int ni=0; ni<4; ni++) {
            float* Cp = out + (size_t)b*SEQ*DIM
                        + (size_t)(i0 + wm*32 + mi*16)*DIM + (n0 + wn*64 + ni*16);
            wmma::store_matrix_sync(Cp, acc[mi][ni], DIM, wmma::mem_row_major);
        }
}

// ---------------- launch ----------------
extern "C" void kernel_launch(void* const* d_in, const int* in_sizes, int n_in,
                              void* d_out, int out_size) {
    (void)in_sizes; (void)n_in; (void)out_size;
    const float* x  = (const float*)d_in[0];
    const float* Wq = (const float*)d_in[1];
    const float* bq = (const float*)d_in[2];
    const float* Wk = (const float*)d_in[3];
    const float* bk = (const float*)d_in[4];
    const float* Wv = (const float*)d_in[5];
    const float* bv = (const float*)d_in[6];
    float* out = (float*)d_out;

    const int nx2 = NTOK*DIM/2;
    const int nw2 = DIM*DIM/2;
    split_kernel<<<(nx2 + 255)/256, 256>>>(x,  0, nx2);
    split_kernel<<<(nw2 + 255)/256, 256>>>(Wq, 1, nw2);
    split_kernel<<<(nw2 + 255)/256, 256>>>(Wk, 2, nw2);
    split_kernel<<<(nw2 + 255)/256, 256>>>(Wv, 3, nw2);

    qkv_kernel<<<dim3(DIM/128, NTOK/128, 3), 256>>>(bq, bk, bv);
    scores_kernel<<<dim3(SEQ/128, SEQ/128, BATCH), 256>>>();
    softmax_kernel<<<NTOK, 256>>>();
    z_kernel<<<dim3(DIM/128, SEQ/128, BATCH), 256>>>(out);
}

// round 16
// speedup vs baseline: 1.9593x; 1.0854x over previous
#include <cuda_runtime.h>
#include <cuda_fp16.h>
#include <mma.h>

using namespace nvcuda;

#define BATCH 4
#define SEQ   4096
#define DIM   512
#define NTOK  (BATCH*SEQ)

// ---------------- scratch (__device__ globals; no allocations anywhere) ----------------
__device__ __half g_xhi[NTOK*DIM];
__device__ __half g_xlo[NTOK*DIM];
__device__ __half g_whi[3*DIM*DIM];
__device__ __half g_wlo[3*DIM*DIM];
__device__ __half g_qhi[NTOK*DIM];
__device__ __half g_qlo[NTOK*DIM];
__device__ __half g_khi[NTOK*DIM];
__device__ __half g_klo[NTOK*DIM];
__device__ __half g_vhi[NTOK*DIM];
__device__ float  g_scores[(size_t)BATCH*SEQ*SEQ];
__device__ __half g_p[(size_t)BATCH*SEQ*SEQ];

// ---------------- cp.async helpers ----------------
__device__ __forceinline__ void cp16(void* dst, const void* src) {
    unsigned sa = (unsigned)__cvta_generic_to_shared(dst);
    asm volatile("cp.async.cg.shared.global [%0], [%1], 16;\n" :: "r"(sa), "l"(src));
}
__device__ __forceinline__ void cp_commit() {
    asm volatile("cp.async.commit_group;\n" ::: "memory");
}
__device__ __forceinline__ void cp_wait0() {
    asm volatile("cp.async.wait_group 0;\n" ::: "memory");
}

// ---------------- fp32 -> fp16 hi/lo split ----------------
__global__ __launch_bounds__(256) void split_kernel(const float* __restrict__ src,
                                                    int which, int n2) {
    int i = blockIdx.x * 256 + threadIdx.x;
    if (i >= n2) return;
    __half *hi, *lo;
    if (which == 0) { hi = g_xhi; lo = g_xlo; }
    else            { hi = g_whi + (which-1)*DIM*DIM; lo = g_wlo + (which-1)*DIM*DIM; }
    float2 v = reinterpret_cast<const float2*>(src)[i];
    __half h0 = __float2half(v.x);
    __half h1 = __float2half(v.y);
    float l0 = v.x - __half2float(h0);
    float l1 = v.y - __half2float(h1);
    reinterpret_cast<__half2*>(hi)[i] = __halves2half2(h0, h1);
    reinterpret_cast<__half2*>(lo)[i] =
        __halves2half2(__float2half(l0), __float2half(l1));
}

// =====================================================================================
// GEMM 1: QKV projection (NN). C[NTOK,DIM] = X @ W + bias, 128x128 blocks, cp.async.
// Q,K: 3-term fp16 split (hh + hl + lh). V (z==2): 2-term (hh + hl), hi-only output.
// =====================================================================================
__global__ __launch_bounds__(256) void qkv_kernel(const float* __restrict__ bq,
                                                  const float* __restrict__ bk,
                                                  const float* __restrict__ bv) {
    __shared__ __half Ah[2][128*24], Al[2][128*24];
    __shared__ __half Bh[2][16*136], Bl[2][16*136];

    const int z  = blockIdx.z;
    const int n0 = blockIdx.x * 128;
    const int i0 = blockIdx.y * 128;
    const int t  = threadIdx.x;
    const int wid = t >> 5, lane = t & 31;
    const int wm = wid >> 1, wn = wid & 1;           // 4x2 warp grid, warp tile 32x64

    const __half* __restrict__ Agh = g_xhi;
    const __half* __restrict__ Agl = g_xlo;
    const __half* __restrict__ Bgh = g_whi + z*DIM*DIM;
    const __half* __restrict__ Bgl = g_wlo + z*DIM*DIM;
    const float* bias = (z==0) ? bq : (z==1) ? bk : bv;
    __half* Oh = (z==0) ? g_qhi : (z==1) ? g_khi : g_vhi;
    __half* Ol = (z==0) ? g_qlo : g_klo;   // unused for z==2
    const bool full3 = (z != 2);

    wmma::fragment<wmma::accumulator,16,16,16,float> acc[2][4];
    #pragma unroll
    for (int mi=0; mi<2; mi++)
        #pragma unroll
        for (int ni=0; ni<4; ni++)
            wmma::fill_fragment(acc[mi][ni], 0.0f);

    const int arow = t >> 1, aseg = t & 1;           // A: 128 rows x 2 chunks of 8
    const int brow = t >> 4, bseg = t & 15;          // B: 16 rows x 16 chunks

    auto load_stage = [&](int kt, int s) {
        int k0 = kt * 16;
        cp16(&Ah[s][arow*24 + aseg*8], Agh + (size_t)(i0+arow)*DIM + k0 + aseg*8);
        cp16(&Al[s][arow*24 + aseg*8], Agl + (size_t)(i0+arow)*DIM + k0 + aseg*8);
        cp16(&Bh[s][brow*136 + bseg*8], Bgh + (size_t)(k0+brow)*DIM + n0 + bseg*8);
        cp16(&Bl[s][brow*136 + bseg*8], Bgl + (size_t)(k0+brow)*DIM + n0 + bseg*8);
        cp_commit();
    };

    const int KSTEPS = DIM/16;
    load_stage(0, 0);
    for (int kt = 0; kt < KSTEPS; kt++) {
        cp_wait0();
        __syncthreads();
        const int cur = kt & 1;
        if (kt+1 < KSTEPS) load_stage(kt+1, cur^1);

        wmma::fragment<wmma::matrix_a,16,16,16,__half,wmma::row_major> fah[2], fal[2];
        wmma::fragment<wmma::matrix_b,16,16,16,__half,wmma::row_major> fbh[4], fbl[4];
        #pragma unroll
        for (int mi=0; mi<2; mi++) {
            wmma::load_matrix_sync(fah[mi], &Ah[cur][(wm*32+mi*16)*24], 24);
            if (full3)
                wmma::load_matrix_sync(fal[mi], &Al[cur][(wm*32+mi*16)*24], 24);
        }
        #pragma unroll
        for (int ni=0; ni<4; ni++) {
            wmma::load_matrix_sync(fbh[ni], &Bh[cur][wn*64+ni*16], 136);
            wmma::load_matrix_sync(fbl[ni], &Bl[cur][wn*64+ni*16], 136);
        }
        #pragma unroll
        for (int mi=0; mi<2; mi++)
            #pragma unroll
            for (int ni=0; ni<4; ni++) {
                wmma::mma_sync(acc[mi][ni], fah[mi], fbh[ni], acc[mi][ni]);
                wmma::mma_sync(acc[mi][ni], fah[mi], fbl[ni], acc[mi][ni]);
                if (full3)
                    wmma::mma_sync(acc[mi][ni], fal[mi], fbh[ni], acc[mi][ni]);
            }
    }

    // epilogue: stage each 16x16 fragment (reusing Ah smem), add bias, split to hi/lo
    __syncthreads();
    float* buf = reinterpret_cast<float*>(&Ah[0][0]) + wid * (16*20);
    #pragma unroll
    for (int mi=0; mi<2; mi++)
        #pragma unroll
        for (int ni=0; ni<4; ni++) {
            wmma::store_matrix_sync(buf, acc[mi][ni], 20, wmma::mem_row_major);
            __syncwarp();
            int gi = i0 + wm*32 + mi*16;
            int gn = n0 + wn*64 + ni*16;
            for (int e = lane; e < 256; e += 32) {
                int r = e >> 4, c = e & 15;
                float v = buf[r*20 + c] + bias[gn + c];
                __half h = __float2half(v);
                size_t off = (size_t)(gi + r)*DIM + gn + c;
                Oh[off] = h;
                if (full3) {
                    float l = v - __half2float(h);
                    Ol[off] = __float2half(l);
                }
            }
            __syncwarp();
        }
}

// =====================================================================================
// GEMM 2: scores = Q @ K^T * 0.5 (NT). 128x128 blocks, cp.async, fp32 out. 3-term.
// =====================================================================================
__global__ __launch_bounds__(256) void scores_kernel() {
    __shared__ __half Ah[2][128*24], Al[2][128*24];
    __shared__ __half Bh[2][128*24], Bl[2][128*24];

    const int b  = blockIdx.z;
    const int j0 = blockIdx.x * 128;
    const int i0 = blockIdx.y * 128;
    const int t  = threadIdx.x;
    const int wid = t >> 5;
    const int wm = wid >> 1, wn = wid & 1;

    const __half* __restrict__ Agh = g_qhi + (size_t)b*SEQ*DIM;
    const __half* __restrict__ Agl = g_qlo + (size_t)b*SEQ*DIM;
    const __half* __restrict__ Bgh = g_khi + (size_t)b*SEQ*DIM;
    const __half* __restrict__ Bgl = g_klo + (size_t)b*SEQ*DIM;

    wmma::fragment<wmma::accumulator,16,16,16,float> acc[2][4];
    #pragma unroll
    for (int mi=0; mi<2; mi++)
        #pragma unroll
        for (int ni=0; ni<4; ni++)
            wmma::fill_fragment(acc[mi][ni], 0.0f);

    const int arow = t >> 1, aseg = t & 1;   // both tiles: 128 rows x 2 chunks

    auto load_stage = [&](int kt, int s) {
        int k0 = kt * 16;
        cp16(&Ah[s][arow*24 + aseg*8], Agh + (size_t)(i0+arow)*DIM + k0 + aseg*8);
        cp16(&Al[s][arow*24 + aseg*8], Agl + (size_t)(i0+arow)*DIM + k0 + aseg*8);
        cp16(&Bh[s][arow*24 + aseg*8], Bgh + (size_t)(j0+arow)*DIM + k0 + aseg*8);
        cp16(&Bl[s][arow*24 + aseg*8], Bgl + (size_t)(j0+arow)*DIM + k0 + aseg*8);
        cp_commit();
    };

    const int KSTEPS = DIM/16;
    load_stage(0, 0);
    for (int kt = 0; kt < KSTEPS; kt++) {
        cp_wait0();
        __syncthreads();
        const int cur = kt & 1;
        if (kt+1 < KSTEPS) load_stage(kt+1, cur^1);

        wmma::fragment<wmma::matrix_a,16,16,16,__half,wmma::row_major> fah[2], fal[2];
        wmma::fragment<wmma::matrix_b,16,16,16,__half,wmma::col_major> fbh[4], fbl[4];
        #pragma unroll
        for (int mi=0; mi<2; mi++) {
            wmma::load_matrix_sync(fah[mi], &Ah[cur][(wm*32+mi*16)*24], 24);
            wmma::load_matrix_sync(fal[mi], &Al[cur][(wm*32+mi*16)*24], 24);
        }
        #pragma unroll
        for (int ni=0; ni<4; ni++) {
            wmma::load_matrix_sync(fbh[ni], &Bh[cur][(wn*64+ni*16)*24], 24);
            wmma::load_matrix_sync(fbl[ni], &Bl[cur][(wn*64+ni*16)*24], 24);
        }
        #pragma unroll
        for (int mi=0; mi<2; mi++)
            #pragma unroll
            for (int ni=0; ni<4; ni++) {
                wmma::mma_sync(acc[mi][ni], fah[mi], fbh[ni], acc[mi][ni]);
                wmma::mma_sync(acc[mi][ni], fah[mi], fbl[ni], acc[mi][ni]);
                wmma::mma_sync(acc[mi][ni], fal[mi], fbh[ni], acc[mi][ni]);
            }
    }

    #pragma unroll
    for (int mi=0; mi<2; mi++)
        #pragma unroll
        for (int ni=0; ni<4; ni++) {
            #pragma unroll
            for (int e = 0; e < acc[mi][ni].num_elements; e++)
                acc[mi][ni].x[e] *= 0.5f;    // scale = batch/2 = 2 -> divide by 2
            float* Cp = g_scores + (size_t)b*SEQ*SEQ
                        + (size_t)(i0 + wm*32 + mi*16)*SEQ + (j0 + wn*64 + ni*16);
            wmma::store_matrix_sync(Cp, acc[mi][ni], SEQ, wmma::mem_row_major);
        }
}

// ---------------- softmax over rows of 4096, writes P as single fp16 ----------------
__global__ __launch_bounds__(256) void softmax_kernel() {
    __shared__ float red[40];
    const int t = threadIdx.x;
    const int lane = t & 31, warp = t >> 5;
    size_t base = (size_t)blockIdx.x * SEQ;
    const float4* src4 = reinterpret_cast<const float4*>(g_scores + base);

    float4 v[4];
    float mx = -3.0e38f;
    #pragma unroll
    for (int q = 0; q < 4; q++) {
        v[q] = src4[t + 256*q];
        mx = fmaxf(mx, fmaxf(fmaxf(v[q].x, v[q].y), fmaxf(v[q].z, v[q].w)));
    }
    #pragma unroll
    for (int o = 16; o > 0; o >>= 1) mx = fmaxf(mx, __shfl_xor_sync(0xffffffffu, mx, o));
    if (lane == 0) red[warp] = mx;
    __syncthreads();
    if (t == 0) {
        float m = red[0];
        #pragma unroll
        for (int w = 1; w < 8; w++) m = fmaxf(m, red[w]);
        red[32] = m;
    }
    __syncthreads();
    mx = red[32];

    float sum = 0.0f;
    #pragma unroll
    for (int q = 0; q < 4; q++) {
        v[q].x = expf(v[q].x - mx);
        v[q].y = expf(v[q].y - mx);
        v[q].z = expf(v[q].z - mx);
        v[q].w = expf(v[q].w - mx);
        sum += (v[q].x + v[q].y) + (v[q].z + v[q].w);
    }
    #pragma unroll
    for (int o = 16; o > 0; o >>= 1) sum += __shfl_xor_sync(0xffffffffu, sum, o);
    if (lane == 0) red[8 + warp] = sum;
    __syncthreads();
    if (t == 0) {
        float s = 0.0f;
        #pragma unroll
        for (int w = 0; w < 8; w++) s += red[8 + w];
        red[33] = 1.0f / s;
    }
    __syncthreads();
    float inv = red[33];

    __half2* ph = reinterpret_cast<__half2*>(g_p + base);
    #pragma unroll
    for (int q = 0; q < 4; q++) {
        float p0 = v[q].x * inv, p1 = v[q].y * inv, p2 = v[q].z * inv, p3 = v[q].w * inv;
        int pi = 2*(t + 256*q);
        ph[pi]   = __floats2half2_rn(p0, p1);
        ph[pi+1] = __floats2half2_rn(p2, p3);
    }
}

// =====================================================================================
// GEMM 3: Z = P @ V (NN), K = 4096. 1-term: P_h * V_h.
// =====================================================================================
__global__ __launch_bounds__(256) void z_kernel(float* __restrict__ out) {
    __shared__ __half As[2][128*24];
    __shared__ __half Bs[2][16*136];

    const int b  = blockIdx.z;
    const int n0 = blockIdx.x * 128;
    const int i0 = blockIdx.y * 128;
    const int t  = threadIdx.x;
    const int wid = t >> 5;
    const int wm = wid >> 1, wn = wid & 1;

    const __half* __restrict__ Ag = g_p   + (size_t)b*SEQ*SEQ;
    const __half* __restrict__ Bg = g_vhi + (size_t)b*SEQ*DIM;

    wmma::fragment<wmma::accumulator,16,16,16,float> acc[2][4];
    #pragma unroll
    for (int mi=0; mi<2; mi++)
        #pragma unroll
        for (int ni=0; ni<4; ni++)
            wmma::fill_fragment(acc[mi][ni], 0.0f);

    const int arow = t >> 1, aseg = t & 1;   // A: 128 rows x 2 chunks
    const int brow = t >> 4, bseg = t & 15;  // B: 16 rows x 16 chunks

    auto load_stage = [&](int kt, int s) {
        int k0 = kt * 16;
        cp16(&As[s][arow*24 + aseg*8], Ag + (size_t)(i0+arow)*SEQ + k0 + aseg*8);
        cp16(&Bs[s][brow*136 + bseg*8], Bg + (size_t)(k0+brow)*DIM + n0 + bseg*8);
        cp_commit();
    };

    const int KSTEPS = SEQ/16;
    load_stage(0, 0);
    for (int kt = 0; kt < KSTEPS; kt++) {
        cp_wait0();
        __syncthreads();
        const int cur = kt & 1;
        if (kt+1 < KSTEPS) load_stage(kt+1, cur^1);

        wmma::fragment<wmma::matrix_a,16,16,16,__half,wmma::row_major> fa[2];
        wmma::fragment<wmma::matrix_b,16,16,16,__half,wmma::row_major> fb[4];
        #pragma unroll
        for (int mi=0; mi<2; mi++)
            wmma::load_matrix_sync(fa[mi], &As[cur][(wm*32+mi*16)*24], 24);
        #pragma unroll
        for (int ni=0; ni<4; ni++)
            wmma::load_matrix_sync(fb[ni], &Bs[cur][wn*64+ni*16], 136);
        #pragma unroll
        for (int mi=0; mi<2; mi++)
            #pragma unroll
            for (int ni=0; ni<4; ni++)
                wmma::mma_sync(acc[mi][ni], fa[mi], fb[ni], acc[mi][ni]);
    }

    #pragma unroll
    for (int mi=0; mi<2; mi++)
        #pragma unroll
        for (int ni=0; ni<4; ni++) {
            float* Cp = out + (size_t)b*SEQ*DIM
                        + (size_t)(i0 + wm*32 + mi*16)*DIM + (n0 + wn*64 + ni*16);
            wmma::store_matrix_sync(Cp, acc[mi][ni], DIM, wmma::mem_row_major);
        }
}

// ---------------- launch ----------------
extern "C" void kernel_launch(void* const* d_in, const int* in_sizes, int n_in,
                              void* d_out, int out_size) {
    (void)in_sizes; (void)n_in; (void)out_size;
    const float* x  = (const float*)d_in[0];
    const float* Wq = (const float*)d_in[1];
    const float* bq = (const float*)d_in[2];
    const float* Wk = (const float*)d_in[3];
    const float* bk = (const float*)d_in[4];
    const float* Wv = (const float*)d_in[5];
    const float* bv = (const float*)d_in[6];
    float* out = (float*)d_out;

    const int nx2 = NTOK*DIM/2;
    const int nw2 = DIM*DIM/2;
    split_kernel<<<(nx2 + 255)/256, 256>>>(x,  0, nx2);
    split_kernel<<<(nw2 + 255)/256, 256>>>(Wq, 1, nw2);
    split_kernel<<<(nw2 + 255)/256, 256>>>(Wk, 2, nw2);
    split_kernel<<<(nw2 + 255)/256, 256>>>(Wv, 3, nw2);

    qkv_kernel<<<dim3(DIM/128, NTOK/128, 3), 256>>>(bq, bk, bv);
    scores_kernel<<<dim3(SEQ/128, SEQ/128, BATCH), 256>>>();
    softmax_kernel<<<NTOK, 256>>>();
    z_kernel<<<dim3(DIM/128, SEQ/128, BATCH), 256>>>(out);
}